// round 11
// baseline (speedup 1.0000x reference)
#include <cuda_runtime.h>
#include <math.h>
#include <stdint.h>
typedef unsigned long long ull;

#define SCALE 0.125f
#define EPSA 1e-8f
#define LN_EPS 1e-5f

__device__ __forceinline__ ull fma2(ull a, ull b, ull c){ull d;asm("fma.rn.f32x2 %0,%1,%2,%3;":"=l"(d):"l"(a),"l"(b),"l"(c));return d;}
__device__ __forceinline__ ull add2(ull a, ull b){ull d;asm("add.rn.f32x2 %0,%1,%2;":"=l"(d):"l"(a),"l"(b));return d;}
__device__ __forceinline__ ull pack2(float lo, float hi){ull d;asm("mov.b64 %0,{%1,%2};":"=l"(d):"f"(lo),"f"(hi));return d;}
__device__ __forceinline__ void unpack2(ull v, float& lo, float& hi){asm("mov.b64 {%0,%1},%2;":"=f"(lo),"=f"(hi):"l"(v));}

__device__ __forceinline__ uint32_t smem_u32(const void* p){
    uint32_t a; asm("{.reg .u64 t; cvta.to.shared.u64 t, %1; cvt.u32.u64 %0, t;}" : "=r"(a) : "l"(p)); return a;
}
__device__ __forceinline__ void cp16(uint32_t dst, const void* src){
    asm volatile("cp.async.ca.shared.global [%0], [%1], 16;" :: "r"(dst), "l"(src) : "memory");
}
__device__ __forceinline__ void bulk_cp(uint32_t dst, const void* src, uint32_t bytes, uint32_t mbar){
    asm volatile("cp.async.bulk.shared::cta.global.mbarrier::complete_tx::bytes [%0], [%1], %2, [%3];"
                 :: "r"(dst), "l"(src), "r"(bytes), "r"(mbar) : "memory");
}
__device__ __forceinline__ void mbar_init(uint32_t mbar, uint32_t cnt){
    asm volatile("mbarrier.init.shared.b64 [%0], %1;" :: "r"(mbar), "r"(cnt) : "memory");
}
__device__ __forceinline__ void mbar_expect(uint32_t mbar, uint32_t bytes){
    asm volatile("mbarrier.arrive.expect_tx.shared.b64 _, [%0], %1;" :: "r"(mbar), "r"(bytes) : "memory");
}
__device__ __forceinline__ void mbar_wait0(uint32_t mbar){
    uint32_t done;
    do {
        asm volatile("{\n\t.reg .pred p;\n\t"
                     "mbarrier.try_wait.parity.acquire.cta.shared::cta.b64 p, [%1], 0;\n\t"
                     "selp.b32 %0, 1, 0, p;\n\t}"
                     : "=r"(done) : "r"(mbar) : "memory");
    } while (!done);
}

// device scratch
__device__ float g_slots[64*448];
__device__ ull   g_ug2[64*224];     // pairs of SCALE*u*g_in
__device__ ull   g_ub2[64*7];       // {ub, Su}
__device__ ull   g_P2[1024*224];    // per (b,chunk16) raw-x weighted sums
__device__ ull   g_KD2[1024*7];     // per (b,chunk16) {K, D}

// ---------------------------------------------------------------------------
// attn_pass: grid 1024 = 64 b x 16 chunks of 256 tokens (2 passes x 128).
// Double-buffered cp.async input tiles; XOR-swizzled unpadded Xs; 3 CTAs/SM.
// smem (ull): X0=0[4096], X1=4096[4096], As=8192[128*8], MS=9216[128],
//             Ub=9344[8], Ug=9352[224] -> total 9576 ull = 76,608 B
// ---------------------------------------------------------------------------
__global__ void __launch_bounds__(128,3) attn_pass(const float* __restrict__ inp)
{
    extern __shared__ ull sm[];
    ull* X0 = sm;
    ull* X1 = sm + 4096;
    ull* As = sm + 8192;     // [128][8]: 7 packed {w,w} + pad
    ull* MS = sm + 9216;     // [128] {m,std}
    ull* Ub = sm + 9344;     // [7] {ub,Su} (+1 pad)
    ull* Ug = sm + 9352;     // [7][32]

    int tid = threadIdx.x, blk = blockIdx.x;
    int b = blk >> 4, chunk = blk & 15;

    for (int i = tid; i < 224; i += 128) Ug[i] = g_ug2[b*224 + i];
    if (tid < 7) Ub[tid] = g_ub2[b*7 + tid];

    ull p2[7]; ull kd2 = 0ull;
    #pragma unroll
    for (int i = 0; i < 7; i++) p2[i] = 0ull;

    const char* gsrc = (const char*)inp + (size_t)(b*4096 + chunk*256)*256;
    int w8 = tid >> 5, cp = tid & 31;
    uint32_t xb0 = smem_u32(X0), xb1 = smem_u32(X1);

    // prefetch both pass tiles (swizzled dst), one commit group each
    #pragma unroll
    for (int k = 0; k < 16; k++) {
        int idx = tid + k*128;
        int t = idx >> 4, c = idx & 15;
        uint32_t doff = (uint32_t)(t*32 + 2*(c ^ (t & 15)))*8u;
        cp16(xb0 + doff, gsrc + idx*16);
    }
    asm volatile("cp.async.commit_group;" ::: "memory");
    #pragma unroll
    for (int k = 0; k < 16; k++) {
        int idx = tid + k*128;
        int t = idx >> 4, c = idx & 15;
        uint32_t doff = (uint32_t)(t*32 + 2*(c ^ (t & 15)))*8u;
        cp16(xb1 + doff, gsrc + 32768 + idx*16);
    }
    asm volatile("cp.async.commit_group;" ::: "memory");

    #pragma unroll
    for (int pass = 0; pass < 2; pass++) {
        if (pass == 0) asm volatile("cp.async.wait_group 1;" ::: "memory");
        else           asm volatile("cp.async.wait_group 0;" ::: "memory");
        __syncthreads();
        ull* buf = pass ? X1 : X0;
        // ---- token phase: thread t = tid handles token t ----
        {
            int sw = tid & 15;
            ull* xrow = buf + tid*32;
            ull sa = 0ull, qa = 0ull, acc[7];
            #pragma unroll
            for (int i = 0; i < 7; i++) acc[i] = 0ull;
            #pragma unroll
            for (int q2 = 0; q2 < 16; q2++) {
                ulonglong2 xv = *reinterpret_cast<const ulonglong2*>(xrow + 2*(q2 ^ sw));
                sa = add2(add2(sa, xv.x), xv.y);
                qa = fma2(xv.y, xv.y, fma2(xv.x, xv.x, qa));
                #pragma unroll
                for (int i = 0; i < 7; i++) {
                    ulonglong2 u = *reinterpret_cast<const ulonglong2*>(Ug + i*32 + q2*2);
                    acc[i] = fma2(xv.y, u.y, fma2(xv.x, u.x, acc[i]));
                }
            }
            float s0,s1,q0,q1; unpack2(sa,s0,s1); unpack2(qa,q0,q1);
            float m    = (s0 + s1) * 0.015625f;
            float varr = fmaf(-m, m, (q0 + q1) * 0.015625f) + LN_EPS;
            float inv  = rsqrtf(varr);
            float stdv = varr * inv;
            float d[7];
            #pragma unroll
            for (int i = 0; i < 7; i++) {
                float a0,a1,ub,su;
                unpack2(acc[i], a0, a1);
                unpack2(Ub[i], ub, su);
                d[i] = fmaf(fmaf(-m, su, a0 + a1), inv, ub);
            }
            float mx = d[0];
            #pragma unroll
            for (int i = 1; i < 7; i++) mx = fmaxf(mx, d[i]);
            float e[7], se = 0.f;
            #pragma unroll
            for (int i = 0; i < 7; i++) { e[i] = __expf(d[i] - mx); se += e[i]; }
            float rinv = 1.0f / se;
            float wv[7];
            #pragma unroll
            for (int i = 0; i < 7; i++) wv[i] = fmaf(e[i], rinv, EPSA) * inv;
            ull* arow = As + tid*8;
            *reinterpret_cast<ulonglong2*>(arow + 0) =
                make_ulonglong2(pack2(wv[0],wv[0]), pack2(wv[1],wv[1]));
            *reinterpret_cast<ulonglong2*>(arow + 2) =
                make_ulonglong2(pack2(wv[2],wv[2]), pack2(wv[3],wv[3]));
            *reinterpret_cast<ulonglong2*>(arow + 4) =
                make_ulonglong2(pack2(wv[4],wv[4]), pack2(wv[5],wv[5]));
            *reinterpret_cast<ulonglong2*>(arow + 6) =
                make_ulonglong2(pack2(wv[6],wv[6]), pack2(wv[6],wv[6]));
            MS[tid] = pack2(m, stdv);
        }
        __syncthreads();
        // ---- P phase: warp w8 -> tokens [w8*32, +32), lane cp = logical ull ----
        {
            int tb = w8 * 32;
            int phalf = cp & 1, ppair = cp >> 1;
            #pragma unroll 4
            for (int j = 0; j < 32; j++) {
                int t = tb + j;
                ull xv = buf[t*32 + 2*(ppair ^ (t & 15)) + phalf];
                const ulonglong2* ap = reinterpret_cast<const ulonglong2*>(As + t*8);
                ulonglong2 a01 = ap[0], a23 = ap[1], a45 = ap[2];
                ull a6 = As[t*8 + 6];
                p2[0] = fma2(a01.x, xv, p2[0]);
                p2[1] = fma2(a01.y, xv, p2[1]);
                p2[2] = fma2(a23.x, xv, p2[2]);
                p2[3] = fma2(a23.y, xv, p2[3]);
                p2[4] = fma2(a45.x, xv, p2[4]);
                p2[5] = fma2(a45.y, xv, p2[5]);
                p2[6] = fma2(a6,    xv, p2[6]);
            }
        }
        // ---- KD phase: {K,D} += {w,w} * {m,std} ----
        if (tid < 112) {
            int i = tid >> 4, tg = tid & 15;
            #pragma unroll
            for (int j = 0; j < 8; j++) {
                int t = j*16 + tg;
                kd2 = fma2(As[t*8 + i], MS[t], kd2);
            }
        }
    }
    __syncthreads();
    #pragma unroll
    for (int i = 0; i < 7; i++) X0[w8*224 + i*32 + cp] = p2[i];
    ull* redKD = X0 + 896;
    if (tid < 112) redKD[tid] = kd2;
    __syncthreads();
    for (int o = tid; o < 224; o += 128) {
        ull s = 0ull;
        #pragma unroll
        for (int h = 0; h < 4; h++) s = add2(s, X0[h*224 + o]);
        g_P2[blk*224 + o] = s;
    }
    if (tid >= 112 && tid < 119) {
        int i = tid - 112;
        ull s = 0ull;
        #pragma unroll
        for (int tg = 0; tg < 16; tg++) s = add2(s, redKD[i*16 + tg]);
        g_KD2[blk*7 + i] = s;
    }
}

// ---------------------------------------------------------------------------
// slot-side (exact R8 config): weights bulk-copied RAW; rotated GEMVs.
// ---------------------------------------------------------------------------
#define OWQ   0        // 64x64
#define OWK   4096     // 64x64
#define OWV   8192     // 64x64
#define OWIH  12288    // 192x64
#define OWHH  24576    // 192x64
#define OW1   36864    // 128x64
#define OW2   45056    // 64x128
#define OXA   53248    // 448: sxa / prep-sS
#define OUPD  53696    // 448: supd / prep-sQ
#define OH    54144    // 448: h / new slots
#define ONEW  54592    // 448
#define OY1   55040    // 896: y1 / prep-sU
#define SLOT_SMEM (55936*4)

__device__ __forceinline__ void warp_ln(const float* src, float* dst,
                                        const float* __restrict__ g,
                                        const float* __restrict__ be,
                                        int w, int lane) {
    float v0 = src[w*64 + lane], v1 = src[w*64 + 32 + lane];
    float s = v0 + v1, ss = v0*v0 + v1*v1;
    #pragma unroll
    for (int o = 16; o; o >>= 1) {
        s  += __shfl_xor_sync(0xffffffffu, s,  o);
        ss += __shfl_xor_sync(0xffffffffu, ss, o);
    }
    float m   = s * 0.015625f;
    float inv = rsqrtf(ss * 0.015625f - m*m + LN_EPS);
    dst[w*64 + lane]      = (v0 - m)*inv*g[lane]      + be[lane];
    dst[w*64 + 32 + lane] = (v1 - m)*inv*g[lane + 32] + be[lane + 32];
}

__device__ __forceinline__ float rotdot64(const float* Wrow, const float* v, int c) {
    float a0 = 0.f, a1 = 0.f;
    #pragma unroll 8
    for (int s = 0; s < 64; s += 2) {
        int d0 = (c + s) & 63, d1 = (c + s + 1) & 63;
        a0 = fmaf(Wrow[d0], v[d0], a0);
        a1 = fmaf(Wrow[d1], v[d1], a1);
    }
    return a0 + a1;
}

__device__ void do_prep(int b, int tid, float* fs,
                        const float* __restrict__ bq, const float* __restrict__ bk,
                        const float* __restrict__ gsl, const float* __restrict__ besl,
                        const float* __restrict__ gin, const float* __restrict__ bein)
{
    float* sS = fs + OXA;
    float* sQ = fs + OUPD;
    float* sU = fs + OY1;
    int w = tid >> 5, lane = tid & 31;
    if (w < 7) warp_ln(fs + OH, sS, gsl, besl, w, lane);
    __syncthreads();
    if (tid < 448) {
        int i = tid >> 6, c = tid & 63;
        sQ[tid] = bq[c] + rotdot64(fs + OWQ + c*64, sS + i*64, c);
    }
    __syncthreads();
    if (tid < 448) {
        int i = tid >> 6, e = tid & 63;
        float a0 = 0.f, a1 = 0.f;
        #pragma unroll 8
        for (int c = 0; c < 64; c += 2) {
            a0 = fmaf(sQ[i*64 + c],   fs[OWK + c*64 + e],     a0);
            a1 = fmaf(sQ[i*64 + c+1], fs[OWK + (c+1)*64 + e], a1);
        }
        float u = a0 + a1;
        sU[tid] = u;
        ((float*)g_ug2)[b*448 + tid] = u * gin[e] * SCALE;
    }
    __syncthreads();
    if (w < 7) {
        float u0 = sU[w*64 + lane], u1 = sU[w*64 + 32 + lane];
        float su = u0*gin[lane]  + u1*gin[lane + 32];
        float ub = u0*bein[lane] + u1*bein[lane + 32]
                 + sQ[w*64 + lane]*bk[lane] + sQ[w*64 + 32 + lane]*bk[lane + 32];
        #pragma unroll
        for (int o = 16; o; o >>= 1) {
            su += __shfl_xor_sync(0xffffffffu, su, o);
            ub += __shfl_xor_sync(0xffffffffu, ub, o);
        }
        if (lane == 0) g_ub2[b*7 + w] = pack2(SCALE*ub, SCALE*su);
    }
}

__global__ void __launch_bounds__(512,1)
slot_begin(const float* __restrict__ noise, const float* __restrict__ mu,
           const float* __restrict__ sigma,
           const float* __restrict__ Wq, const float* __restrict__ bq,
           const float* __restrict__ Wk, const float* __restrict__ bk,
           const float* __restrict__ gsl, const float* __restrict__ besl,
           const float* __restrict__ gin, const float* __restrict__ bein)
{
    extern __shared__ float fs[];
    __shared__ ull mbar_s;
    int b = blockIdx.x, tid = threadIdx.x;
    uint32_t sbase = smem_u32(fs);
    uint32_t mbar  = smem_u32(&mbar_s);
    if (tid == 0) mbar_init(mbar, 1);
    __syncthreads();
    if (tid == 0) {
        mbar_expect(mbar, 2*16384);
        bulk_cp(sbase + OWQ*4, Wq, 16384, mbar);
        bulk_cp(sbase + OWK*4, Wk, 16384, mbar);
    }
    if (tid < 448) {
        int c = tid & 63;
        float v = fmaf(sigma[c], noise[b*448 + tid], mu[c]);
        g_slots[b*448 + tid] = v;
        fs[OH + tid] = v;
    }
    __syncthreads();
    mbar_wait0(mbar);
    do_prep(b, tid, fs, bq, bk, gsl, besl, gin, bein);
}

__global__ void __launch_bounds__(512,1)
slot_step(const float* __restrict__ Wv, const float* __restrict__ bv,
          const float* __restrict__ W_ih, const float* __restrict__ W_hh,
          const float* __restrict__ b_ih, const float* __restrict__ b_hh,
          const float* __restrict__ W1, const float* __restrict__ b1,
          const float* __restrict__ W2, const float* __restrict__ b2,
          const float* __restrict__ gin, const float* __restrict__ bein,
          const float* __restrict__ gff, const float* __restrict__ beff,
          const float* __restrict__ Wq, const float* __restrict__ bq,
          const float* __restrict__ Wk, const float* __restrict__ bk,
          const float* __restrict__ gsl, const float* __restrict__ besl,
          float* __restrict__ outp, int doprep)
{
    extern __shared__ float fs[];
    __shared__ ull mbar_s;
    __shared__ float sK[7], sD[7];
    float* sxa  = fs + OXA;
    float* supd = fs + OUPD;
    float* sh   = fs + OH;
    float* snew = fs + ONEW;
    float* sff  = fs + OXA;
    float* sy1  = fs + OY1;
    int b = blockIdx.x, tid = threadIdx.x;
    int w = tid >> 5, lane = tid & 31;
    const float* gP = (const float*)g_P2;
    uint32_t sbase = smem_u32(fs);
    uint32_t mbar  = smem_u32(&mbar_s);

    if (tid == 0) mbar_init(mbar, 1);
    __syncthreads();
    if (tid == 0) {
        uint32_t total = 16384 + 2*49152 + 32768 + 32768 + (doprep ? 2*16384 : 0);
        mbar_expect(mbar, total);
        bulk_cp(sbase + OWV*4,  Wv,   16384, mbar);
        bulk_cp(sbase + OWIH*4, W_ih, 49152, mbar);
        bulk_cp(sbase + OWHH*4, W_hh, 49152, mbar);
        bulk_cp(sbase + OW1*4,  W1,   32768, mbar);
        bulk_cp(sbase + OW2*4,  W2,   32768, mbar);
        if (doprep) {
            bulk_cp(sbase + OWQ*4, Wq, 16384, mbar);
            bulk_cp(sbase + OWK*4, Wk, 16384, mbar);
        }
    }

    // P0: reduce partials (16 chunks; overlaps bulk copies)
    if (tid < 448) {
        float s = 0.f;
        #pragma unroll
        for (int ch = 0; ch < 16; ch++) s += gP[(b*16 + ch)*448 + tid];
        sxa[tid] = s;
        sh[tid]  = g_slots[b*448 + tid];
    }
    if (tid < 7) {
        float K = 0.f, D = 0.f;
        #pragma unroll
        for (int ch = 0; ch < 16; ch++) {
            float k0, d0; unpack2(g_KD2[(b*16 + ch)*7 + tid], k0, d0);
            K += k0; D += d0;
        }
        sK[tid] = K; sD[tid] = D;
    }
    __syncthreads();
    // P1
    if (tid < 448) {
        int e = tid & 63, i = tid >> 6;
        sxa[tid] = fmaf((sxa[tid] - sK[i]) / sD[i], gin[e], bein[e]);
    }
    __syncthreads();
    mbar_wait0(mbar);
    // P2: upd = xa @ Wv^T + bv
    if (tid < 448) {
        int c = tid & 63, i = tid >> 6;
        supd[tid] = bv[c] + rotdot64(fs + OWV + c*64, sxa + i*64, c);
    }
    __syncthreads();
    // P3: fused GRU
    if (tid < 448) {
        int c = tid & 63, i = tid >> 6;
        const float* wir = fs + OWIH + c*64;
        const float* wiz = fs + OWIH + (64 + c)*64;
        const float* win = fs + OWIH + (128 + c)*64;
        const float* whr = fs + OWHH + c*64;
        const float* whz = fs + OWHH + (64 + c)*64;
        const float* whn = fs + OWHH + (128 + c)*64;
        const float* xu = supd + i*64;
        const float* hh = sh + i*64;
        float gir = 0.f, giz = 0.f, gin_ = 0.f, ghr = 0.f, ghz = 0.f, ghn = 0.f;
        #pragma unroll 8
        for (int s = 0; s < 64; s++) {
            int d = (c + s) & 63;
            float xv = xu[d], hv = hh[d];
            gir = fmaf(xv, wir[d], gir);
            giz = fmaf(xv, wiz[d], giz);
            gin_ = fmaf(xv, win[d], gin_);
            ghr = fmaf(hv, whr[d], ghr);
            ghz = fmaf(hv, whz[d], ghz);
            ghn = fmaf(hv, whn[d], ghn);
        }
        gir += b_ih[c];        ghr += b_hh[c];
        giz += b_ih[64 + c];   ghz += b_hh[64 + c];
        gin_ += b_ih[128 + c]; ghn += b_hh[128 + c];
        float rg = 1.0f / (1.0f + __expf(-(gir + ghr)));
        float zg = 1.0f / (1.0f + __expf(-(giz + ghz)));
        float ng = tanhf(fmaf(rg, ghn, gin_));
        snew[tid] = fmaf(zg, sh[tid] - ng, ng);
    }
    __syncthreads();
    // P4
    if (w < 7) warp_ln(snew, sff, gff, beff, w, lane);
    __syncthreads();
    // P5
    for (int idx = tid; idx < 896; idx += 512) {
        int i = idx >> 7, r = idx & 127;
        const float* wr = fs + OW1 + r*64;
        const float* v  = sff + i*64;
        float a0 = 0.f, a1 = 0.f;
        #pragma unroll 8
        for (int s = 0; s < 64; s += 2) {
            int d0 = (r + s) & 63, d1 = (r + s + 1) & 63;
            a0 = fmaf(wr[d0], v[d0], a0);
            a1 = fmaf(wr[d1], v[d1], a1);
        }
        sy1[idx] = fmaxf(b1[r] + a0 + a1, 0.0f);
    }
    __syncthreads();
    // P6
    if (tid < 448) {
        int c = tid & 63, i = tid >> 6;
        const float* wr = fs + OW2 + c*128;
        const float* v  = sy1 + i*128;
        float a0 = 0.f, a1 = 0.f;
        #pragma unroll 8
        for (int s = 0; s < 128; s += 2) {
            int d0 = (c + s) & 127, d1 = (c + s + 1) & 127;
            a0 = fmaf(wr[d0], v[d0], a0);
            a1 = fmaf(wr[d1], v[d1], a1);
        }
        float vout = snew[tid] + b2[c] + a0 + a1;
        g_slots[b*448 + tid] = vout;
        sh[tid] = vout;
        if (outp) outp[b*448 + tid] = vout;
    }
    if (doprep) {
        __syncthreads();
        do_prep(b, tid, fs, bq, bk, gsl, besl, gin, bein);
    }
}

// ---------------------------------------------------------------------------
extern "C" void kernel_launch(void* const* d_in, const int* in_sizes, int n_in,
                              void* d_out, int out_size)
{
    const float* inputs = (const float*)d_in[0];
    const float* noise  = (const float*)d_in[2];
    const float* mu     = (const float*)d_in[3];
    const float* sigma  = (const float*)d_in[4];
    const float* Wq     = (const float*)d_in[5];
    const float* bq     = (const float*)d_in[6];
    const float* Wk     = (const float*)d_in[7];
    const float* bk     = (const float*)d_in[8];
    const float* Wv     = (const float*)d_in[9];
    const float* bv     = (const float*)d_in[10];
    const float* W_ih   = (const float*)d_in[11];
    const float* W_hh   = (const float*)d_in[12];
    const float* b_ih   = (const float*)d_in[13];
    const float* b_hh   = (const float*)d_in[14];
    const float* W1     = (const float*)d_in[15];
    const float* b1     = (const float*)d_in[16];
    const float* W2     = (const float*)d_in[17];
    const float* b2     = (const float*)d_in[18];
    const float* gin    = (const float*)d_in[19];
    const float* bein   = (const float*)d_in[20];
    const float* gsl    = (const float*)d_in[21];
    const float* besl   = (const float*)d_in[22];
    const float* gff    = (const float*)d_in[23];
    const float* beff   = (const float*)d_in[24];

    const int ATTN_SMEM = 9576 * 8;   // 76,608 B -> 3 CTAs/SM
    static int configured = 0;
    if (!configured) {
        cudaFuncSetAttribute(attn_pass, cudaFuncAttributeMaxDynamicSharedMemorySize, ATTN_SMEM);
        cudaFuncSetAttribute(slot_begin, cudaFuncAttributeMaxDynamicSharedMemorySize, SLOT_SMEM);
        cudaFuncSetAttribute(slot_step, cudaFuncAttributeMaxDynamicSharedMemorySize, SLOT_SMEM);
        configured = 1;
    }

    slot_begin<<<64, 512, SLOT_SMEM>>>(noise, mu, sigma, Wq, bq, Wk, bk,
                                       gsl, besl, gin, bein);
    for (int it = 0; it < 3; it++) {
        attn_pass<<<1024, 128, ATTN_SMEM>>>(inputs);
        slot_step<<<64, 512, SLOT_SMEM>>>(Wv, bv, W_ih, W_hh, b_ih, b_hh,
                                          W1, b1, W2, b2, gin, bein, gff, beff,
                                          Wq, bq, Wk, bk, gsl, besl,
                                          it == 2 ? (float*)d_out : nullptr,
                                          it == 2 ? 0 : 1);
    }
}

// round 13
// speedup vs baseline: 1.0148x; 1.0148x over previous
#include <cuda_runtime.h>
#include <math.h>
#include <stdint.h>
typedef unsigned long long ull;

#define SCALE 0.125f
#define EPSA 1e-8f
#define LN_EPS 1e-5f

__device__ __forceinline__ ull fma2(ull a, ull b, ull c){ull d;asm("fma.rn.f32x2 %0,%1,%2,%3;":"=l"(d):"l"(a),"l"(b),"l"(c));return d;}
__device__ __forceinline__ ull add2(ull a, ull b){ull d;asm("add.rn.f32x2 %0,%1,%2;":"=l"(d):"l"(a),"l"(b));return d;}
__device__ __forceinline__ ull pack2(float lo, float hi){ull d;asm("mov.b64 %0,{%1,%2};":"=l"(d):"f"(lo),"f"(hi));return d;}
__device__ __forceinline__ void unpack2(ull v, float& lo, float& hi){asm("mov.b64 {%0,%1},%2;":"=f"(lo),"=f"(hi):"l"(v));}

__device__ __forceinline__ void ldg_el4(const void* p, ull& a, ull& b, ull& c, ull& d){
    asm volatile("ld.global.L2::evict_last.v4.b64 {%0,%1,%2,%3}, [%4];"
                 : "=l"(a), "=l"(b), "=l"(c), "=l"(d) : "l"(p));
}

__device__ __forceinline__ uint32_t smem_u32(const void* p){
    uint32_t a; asm("{.reg .u64 t; cvta.to.shared.u64 t, %1; cvt.u32.u64 %0, t;}" : "=r"(a) : "l"(p)); return a;
}
__device__ __forceinline__ void bulk_cp(uint32_t dst, const void* src, uint32_t bytes, uint32_t mbar){
    asm volatile("cp.async.bulk.shared::cta.global.mbarrier::complete_tx::bytes [%0], [%1], %2, [%3];"
                 :: "r"(dst), "l"(src), "r"(bytes), "r"(mbar) : "memory");
}
__device__ __forceinline__ void mbar_init(uint32_t mbar, uint32_t cnt){
    asm volatile("mbarrier.init.shared.b64 [%0], %1;" :: "r"(mbar), "r"(cnt) : "memory");
}
__device__ __forceinline__ void mbar_expect(uint32_t mbar, uint32_t bytes){
    asm volatile("mbarrier.arrive.expect_tx.shared.b64 _, [%0], %1;" :: "r"(mbar), "r"(bytes) : "memory");
}
__device__ __forceinline__ void mbar_wait0(uint32_t mbar){
    uint32_t done;
    do {
        asm volatile("{\n\t.reg .pred p;\n\t"
                     "mbarrier.try_wait.parity.acquire.cta.shared::cta.b64 p, [%1], 0;\n\t"
                     "selp.b32 %0, 1, 0, p;\n\t}"
                     : "=r"(done) : "r"(mbar) : "memory");
    } while (!done);
}

// device scratch
__device__ float g_slots[64*448];
__device__ ull   g_ug2[64*224];     // pairs of SCALE*u*g_in
__device__ ull   g_ub2[64*7];       // {ub, Su}
__device__ ull   g_P2[1024*224];    // per (b,chunk16) raw-x weighted sums
__device__ ull   g_KD2[1024*7];     // per (b,chunk16) {K, D}

// ---------------------------------------------------------------------------
// attn_pass (R6/R10 config + 256-bit L2::evict_last input loads):
// grid 1024 = 64 b x 16 chunks of 256 tokens (2 passes x 128).
// CTA = 128 threads, 4 CTAs/SM. Xs rows stride 34 ull; As [token][10].
// ---------------------------------------------------------------------------
__global__ void __launch_bounds__(128,4) attn_pass(const float* __restrict__ inp)
{
    extern __shared__ ull sm[];
    ull* Xs = sm;            // [128][34]: 32 raw-x pairs + {m,std} @32 + pad
    ull* As = sm + 4352;     // [128][10]: 7 packed {w,w} + pad
    ull* Ub = sm + 5632;     // [7] {ub,Su} (+1 pad)
    ull* Ug = sm + 5640;     // [7][32]

    int tid = threadIdx.x, blk = blockIdx.x;
    int b = blk >> 4, chunk = blk & 15;

    for (int i = tid; i < 224; i += 128) Ug[i] = g_ug2[b*224 + i];
    if (tid < 7) Ub[tid] = g_ub2[b*7 + tid];

    ull p2[7]; ull kd2 = 0ull;
    #pragma unroll
    for (int i = 0; i < 7; i++) p2[i] = 0ull;

    const char* gsrc = (const char*)inp + (size_t)(b*4096 + chunk*256)*256;
    int w8 = tid >> 5, cp = tid & 31;

    for (int pass = 0; pass < 2; pass++) {
        __syncthreads();
        const char* src = gsrc + pass*32768;
        #pragma unroll
        for (int k = 0; k < 8; k++) {
            int idx = tid + k*128;
            int t = idx >> 3, c4 = idx & 7;
            ull v0, v1, v2, v3;
            ldg_el4(src + idx*32, v0, v1, v2, v3);
            ull* dst = Xs + t*34 + c4*4;
            *reinterpret_cast<ulonglong2*>(dst)     = make_ulonglong2(v0, v1);
            *reinterpret_cast<ulonglong2*>(dst + 2) = make_ulonglong2(v2, v3);
        }
        __syncthreads();
        // ---- token phase: thread t = tid handles token t ----
        {
            ull* xrow = Xs + tid*34;
            ull sa = 0ull, qa = 0ull, acc[7];
            #pragma unroll
            for (int i = 0; i < 7; i++) acc[i] = 0ull;
            #pragma unroll
            for (int q2 = 0; q2 < 16; q2++) {
                ulonglong2 xv = *reinterpret_cast<const ulonglong2*>(xrow + q2*2);
                sa = add2(add2(sa, xv.x), xv.y);
                qa = fma2(xv.y, xv.y, fma2(xv.x, xv.x, qa));
                #pragma unroll
                for (int i = 0; i < 7; i++) {
                    ulonglong2 u = *reinterpret_cast<const ulonglong2*>(Ug + i*32 + q2*2);
                    acc[i] = fma2(xv.y, u.y, fma2(xv.x, u.x, acc[i]));
                }
            }
            float s0,s1,q0,q1; unpack2(sa,s0,s1); unpack2(qa,q0,q1);
            float m    = (s0 + s1) * 0.015625f;
            float varr = fmaf(-m, m, (q0 + q1) * 0.015625f) + LN_EPS;
            float inv  = rsqrtf(varr);
            float stdv = varr * inv;
            float d[7];
            #pragma unroll
            for (int i = 0; i < 7; i++) {
                float a0,a1,ub,su;
                unpack2(acc[i], a0, a1);
                unpack2(Ub[i], ub, su);
                d[i] = fmaf(fmaf(-m, su, a0 + a1), inv, ub);
            }
            float mx = d[0];
            #pragma unroll
            for (int i = 1; i < 7; i++) mx = fmaxf(mx, d[i]);
            float e[7], se = 0.f;
            #pragma unroll
            for (int i = 0; i < 7; i++) { e[i] = __expf(d[i] - mx); se += e[i]; }
            float rinv = 1.0f / se;
            float wv[7];
            #pragma unroll
            for (int i = 0; i < 7; i++) wv[i] = fmaf(e[i], rinv, EPSA) * inv;
            ull* arow = As + tid*10;
            *reinterpret_cast<ulonglong2*>(arow + 0) =
                make_ulonglong2(pack2(wv[0],wv[0]), pack2(wv[1],wv[1]));
            *reinterpret_cast<ulonglong2*>(arow + 2) =
                make_ulonglong2(pack2(wv[2],wv[2]), pack2(wv[3],wv[3]));
            *reinterpret_cast<ulonglong2*>(arow + 4) =
                make_ulonglong2(pack2(wv[4],wv[4]), pack2(wv[5],wv[5]));
            *reinterpret_cast<ulonglong2*>(arow + 6) =
                make_ulonglong2(pack2(wv[6],wv[6]), pack2(wv[6],wv[6]));
            xrow[32] = pack2(m, stdv);
        }
        __syncthreads();
        // ---- P phase: warp w8 -> tokens [w8*32, +32), lane = column pair ----
        {
            int tb = w8 * 32;
            #pragma unroll 4
            for (int j = 0; j < 32; j++) {
                int t = tb + j;
                ull xv = Xs[t*34 + cp];
                const ulonglong2* ap = reinterpret_cast<const ulonglong2*>(As + t*10);
                ulonglong2 a01 = ap[0], a23 = ap[1], a45 = ap[2];
                ull a6 = As[t*10 + 6];
                p2[0] = fma2(a01.x, xv, p2[0]);
                p2[1] = fma2(a01.y, xv, p2[1]);
                p2[2] = fma2(a23.x, xv, p2[2]);
                p2[3] = fma2(a23.y, xv, p2[3]);
                p2[4] = fma2(a45.x, xv, p2[4]);
                p2[5] = fma2(a45.y, xv, p2[5]);
                p2[6] = fma2(a6,    xv, p2[6]);
            }
        }
        // ---- KD phase: {K,D} += {w,w} * {m,std} ----
        if (tid < 112) {
            int i = tid >> 4, tg = tid & 15;
            #pragma unroll
            for (int j = 0; j < 8; j++) {
                int t = j*16 + tg;
                kd2 = fma2(As[t*10 + i], Xs[t*34 + 32], kd2);
            }
        }
    }
    __syncthreads();
    #pragma unroll
    for (int i = 0; i < 7; i++) Xs[w8*224 + i*32 + cp] = p2[i];
    ull* redKD = Xs + 896;
    if (tid < 112) redKD[tid] = kd2;
    __syncthreads();
    for (int o = tid; o < 224; o += 128) {
        ull s = 0ull;
        #pragma unroll
        for (int h = 0; h < 4; h++) s = add2(s, Xs[h*224 + o]);
        g_P2[blk*224 + o] = s;
    }
    if (tid >= 112 && tid < 119) {
        int i = tid - 112;
        ull s = 0ull;
        #pragma unroll
        for (int tg = 0; tg < 16; tg++) s = add2(s, redKD[i*16 + tg]);
        g_KD2[blk*7 + i] = s;
    }
}

// ---------------------------------------------------------------------------
// slot-side (R8 config): weights bulk-copied RAW; rotated GEMVs.
// ---------------------------------------------------------------------------
#define OWQ   0        // 64x64
#define OWK   4096     // 64x64
#define OWV   8192     // 64x64
#define OWIH  12288    // 192x64
#define OWHH  24576    // 192x64
#define OW1   36864    // 128x64
#define OW2   45056    // 64x128
#define OXA   53248    // 448: sxa / prep-sS
#define OUPD  53696    // 448: supd / prep-sQ
#define OH    54144    // 448: h / new slots
#define ONEW  54592    // 448
#define OY1   55040    // 896: y1 / prep-sU
#define SLOT_SMEM (55936*4)

__device__ __forceinline__ void warp_ln(const float* src, float* dst,
                                        const float* __restrict__ g,
                                        const float* __restrict__ be,
                                        int w, int lane) {
    float v0 = src[w*64 + lane], v1 = src[w*64 + 32 + lane];
    float s = v0 + v1, ss = v0*v0 + v1*v1;
    #pragma unroll
    for (int o = 16; o; o >>= 1) {
        s  += __shfl_xor_sync(0xffffffffu, s,  o);
        ss += __shfl_xor_sync(0xffffffffu, ss, o);
    }
    float m   = s * 0.015625f;
    float inv = rsqrtf(ss * 0.015625f - m*m + LN_EPS);
    dst[w*64 + lane]      = (v0 - m)*inv*g[lane]      + be[lane];
    dst[w*64 + 32 + lane] = (v1 - m)*inv*g[lane + 32] + be[lane + 32];
}

__device__ __forceinline__ float rotdot64(const float* Wrow, const float* v, int c) {
    float a0 = 0.f, a1 = 0.f;
    #pragma unroll 8
    for (int s = 0; s < 64; s += 2) {
        int d0 = (c + s) & 63, d1 = (c + s + 1) & 63;
        a0 = fmaf(Wrow[d0], v[d0], a0);
        a1 = fmaf(Wrow[d1], v[d1], a1);
    }
    return a0 + a1;
}

__device__ void do_prep(int b, int tid, float* fs,
                        const float* __restrict__ bq, const float* __restrict__ bk,
                        const float* __restrict__ gsl, const float* __restrict__ besl,
                        const float* __restrict__ gin, const float* __restrict__ bein)
{
    float* sS = fs + OXA;
    float* sQ = fs + OUPD;
    float* sU = fs + OY1;
    int w = tid >> 5, lane = tid & 31;
    if (w < 7) warp_ln(fs + OH, sS, gsl, besl, w, lane);
    __syncthreads();
    if (tid < 448) {
        int i = tid >> 6, c = tid & 63;
        sQ[tid] = bq[c] + rotdot64(fs + OWQ + c*64, sS + i*64, c);
    }
    __syncthreads();
    if (tid < 448) {
        int i = tid >> 6, e = tid & 63;
        float a0 = 0.f, a1 = 0.f;
        #pragma unroll 8
        for (int c = 0; c < 64; c += 2) {
            a0 = fmaf(sQ[i*64 + c],   fs[OWK + c*64 + e],     a0);
            a1 = fmaf(sQ[i*64 + c+1], fs[OWK + (c+1)*64 + e], a1);
        }
        float u = a0 + a1;
        sU[tid] = u;
        ((float*)g_ug2)[b*448 + tid] = u * gin[e] * SCALE;
    }
    __syncthreads();
    if (w < 7) {
        float u0 = sU[w*64 + lane], u1 = sU[w*64 + 32 + lane];
        float su = u0*gin[lane]  + u1*gin[lane + 32];
        float ub = u0*bein[lane] + u1*bein[lane + 32]
                 + sQ[w*64 + lane]*bk[lane] + sQ[w*64 + 32 + lane]*bk[lane + 32];
        #pragma unroll
        for (int o = 16; o; o >>= 1) {
            su += __shfl_xor_sync(0xffffffffu, su, o);
            ub += __shfl_xor_sync(0xffffffffu, ub, o);
        }
        if (lane == 0) g_ub2[b*7 + w] = pack2(SCALE*ub, SCALE*su);
    }
}

__global__ void __launch_bounds__(512,1)
slot_begin(const float* __restrict__ noise, const float* __restrict__ mu,
           const float* __restrict__ sigma,
           const float* __restrict__ Wq, const float* __restrict__ bq,
           const float* __restrict__ Wk, const float* __restrict__ bk,
           const float* __restrict__ gsl, const float* __restrict__ besl,
           const float* __restrict__ gin, const float* __restrict__ bein)
{
    extern __shared__ float fs[];
    __shared__ ull mbar_s;
    int b = blockIdx.x, tid = threadIdx.x;
    uint32_t sbase = smem_u32(fs);
    uint32_t mbar  = smem_u32(&mbar_s);
    if (tid == 0) mbar_init(mbar, 1);
    __syncthreads();
    if (tid == 0) {
        mbar_expect(mbar, 2*16384);
        bulk_cp(sbase + OWQ*4, Wq, 16384, mbar);
        bulk_cp(sbase + OWK*4, Wk, 16384, mbar);
    }
    if (tid < 448) {
        int c = tid & 63;
        float v = fmaf(sigma[c], noise[b*448 + tid], mu[c]);
        g_slots[b*448 + tid] = v;
        fs[OH + tid] = v;
    }
    __syncthreads();
    mbar_wait0(mbar);
    do_prep(b, tid, fs, bq, bk, gsl, besl, gin, bein);
}

__global__ void __launch_bounds__(512,1)
slot_step(const float* __restrict__ Wv, const float* __restrict__ bv,
          const float* __restrict__ W_ih, const float* __restrict__ W_hh,
          const float* __restrict__ b_ih, const float* __restrict__ b_hh,
          const float* __restrict__ W1, const float* __restrict__ b1,
          const float* __restrict__ W2, const float* __restrict__ b2,
          const float* __restrict__ gin, const float* __restrict__ bein,
          const float* __restrict__ gff, const float* __restrict__ beff,
          const float* __restrict__ Wq, const float* __restrict__ bq,
          const float* __restrict__ Wk, const float* __restrict__ bk,
          const float* __restrict__ gsl, const float* __restrict__ besl,
          float* __restrict__ outp, int doprep)
{
    extern __shared__ float fs[];
    __shared__ ull mbar_s;
    __shared__ float sK[7], sD[7];
    float* sxa  = fs + OXA;
    float* supd = fs + OUPD;
    float* sh   = fs + OH;
    float* snew = fs + ONEW;
    float* sff  = fs + OXA;
    float* sy1  = fs + OY1;
    int b = blockIdx.x, tid = threadIdx.x;
    int w = tid >> 5, lane = tid & 31;
    const float* gP = (const float*)g_P2;
    uint32_t sbase = smem_u32(fs);
    uint32_t mbar  = smem_u32(&mbar_s);

    if (tid == 0) mbar_init(mbar, 1);
    __syncthreads();
    if (tid == 0) {
        uint32_t total = 16384 + 2*49152 + 32768 + 32768 + (doprep ? 2*16384 : 0);
        mbar_expect(mbar, total);
        bulk_cp(sbase + OWV*4,  Wv,   16384, mbar);
        bulk_cp(sbase + OWIH*4, W_ih, 49152, mbar);
        bulk_cp(sbase + OWHH*4, W_hh, 49152, mbar);
        bulk_cp(sbase + OW1*4,  W1,   32768, mbar);
        bulk_cp(sbase + OW2*4,  W2,   32768, mbar);
        if (doprep) {
            bulk_cp(sbase + OWQ*4, Wq, 16384, mbar);
            bulk_cp(sbase + OWK*4, Wk, 16384, mbar);
        }
    }

    // P0: reduce partials (16 chunks; overlaps bulk copies)
    if (tid < 448) {
        float s = 0.f;
        #pragma unroll
        for (int ch = 0; ch < 16; ch++) s += gP[(b*16 + ch)*448 + tid];
        sxa[tid] = s;
        sh[tid]  = g_slots[b*448 + tid];
    }
    if (tid < 7) {
        float K = 0.f, D = 0.f;
        #pragma unroll
        for (int ch = 0; ch < 16; ch++) {
            float k0, d0; unpack2(g_KD2[(b*16 + ch)*7 + tid], k0, d0);
            K += k0; D += d0;
        }
        sK[tid] = K; sD[tid] = D;
    }
    __syncthreads();
    // P1
    if (tid < 448) {
        int e = tid & 63, i = tid >> 6;
        sxa[tid] = fmaf((sxa[tid] - sK[i]) / sD[i], gin[e], bein[e]);
    }
    __syncthreads();
    mbar_wait0(mbar);
    // P2: upd = xa @ Wv^T + bv
    if (tid < 448) {
        int c = tid & 63, i = tid >> 6;
        supd[tid] = bv[c] + rotdot64(fs + OWV + c*64, sxa + i*64, c);
    }
    __syncthreads();
    // P3: fused GRU
    if (tid < 448) {
        int c = tid & 63, i = tid >> 6;
        const float* wir = fs + OWIH + c*64;
        const float* wiz = fs + OWIH + (64 + c)*64;
        const float* win = fs + OWIH + (128 + c)*64;
        const float* whr = fs + OWHH + c*64;
        const float* whz = fs + OWHH + (64 + c)*64;
        const float* whn = fs + OWHH + (128 + c)*64;
        const float* xu = supd + i*64;
        const float* hh = sh + i*64;
        float gir = 0.f, giz = 0.f, gin_ = 0.f, ghr = 0.f, ghz = 0.f, ghn = 0.f;
        #pragma unroll 8
        for (int s = 0; s < 64; s++) {
            int d = (c + s) & 63;
            float xv = xu[d], hv = hh[d];
            gir = fmaf(xv, wir[d], gir);
            giz = fmaf(xv, wiz[d], giz);
            gin_ = fmaf(xv, win[d], gin_);
            ghr = fmaf(hv, whr[d], ghr);
            ghz = fmaf(hv, whz[d], ghz);
            ghn = fmaf(hv, whn[d], ghn);
        }
        gir += b_ih[c];        ghr += b_hh[c];
        giz += b_ih[64 + c];   ghz += b_hh[64 + c];
        gin_ += b_ih[128 + c]; ghn += b_hh[128 + c];
        float rg = 1.0f / (1.0f + __expf(-(gir + ghr)));
        float zg = 1.0f / (1.0f + __expf(-(giz + ghz)));
        float ng = tanhf(fmaf(rg, ghn, gin_));
        snew[tid] = fmaf(zg, sh[tid] - ng, ng);
    }
    __syncthreads();
    // P4
    if (w < 7) warp_ln(snew, sff, gff, beff, w, lane);
    __syncthreads();
    // P5
    for (int idx = tid; idx < 896; idx += 512) {
        int i = idx >> 7, r = idx & 127;
        const float* wr = fs + OW1 + r*64;
        const float* v  = sff + i*64;
        float a0 = 0.f, a1 = 0.f;
        #pragma unroll 8
        for (int s = 0; s < 64; s += 2) {
            int d0 = (r + s) & 63, d1 = (r + s + 1) & 63;
            a0 = fmaf(wr[d0], v[d0], a0);
            a1 = fmaf(wr[d1], v[d1], a1);
        }
        sy1[idx] = fmaxf(b1[r] + a0 + a1, 0.0f);
    }
    __syncthreads();
    // P6
    if (tid < 448) {
        int c = tid & 63, i = tid >> 6;
        const float* wr = fs + OW2 + c*128;
        const float* v  = sy1 + i*128;
        float a0 = 0.f, a1 = 0.f;
        #pragma unroll 8
        for (int s = 0; s < 128; s += 2) {
            int d0 = (c + s) & 127, d1 = (c + s + 1) & 127;
            a0 = fmaf(wr[d0], v[d0], a0);
            a1 = fmaf(wr[d1], v[d1], a1);
        }
        float vout = snew[tid] + b2[c] + a0 + a1;
        g_slots[b*448 + tid] = vout;
        sh[tid] = vout;
        if (outp) outp[b*448 + tid] = vout;
    }
    if (doprep) {
        __syncthreads();
        do_prep(b, tid, fs, bq, bk, gsl, besl, gin, bein);
    }
}

// ---------------------------------------------------------------------------
extern "C" void kernel_launch(void* const* d_in, const int* in_sizes, int n_in,
                              void* d_out, int out_size)
{
    const float* inputs = (const float*)d_in[0];
    const float* noise  = (const float*)d_in[2];
    const float* mu     = (const float*)d_in[3];
    const float* sigma  = (const float*)d_in[4];
    const float* Wq     = (const float*)d_in[5];
    const float* bq     = (const float*)d_in[6];
    const float* Wk     = (const float*)d_in[7];
    const float* bk     = (const float*)d_in[8];
    const float* Wv     = (const float*)d_in[9];
    const float* bv     = (const float*)d_in[10];
    const float* W_ih   = (const float*)d_in[11];
    const float* W_hh   = (const float*)d_in[12];
    const float* b_ih   = (const float*)d_in[13];
    const float* b_hh   = (const float*)d_in[14];
    const float* W1     = (const float*)d_in[15];
    const float* b1     = (const float*)d_in[16];
    const float* W2     = (const float*)d_in[17];
    const float* b2     = (const float*)d_in[18];
    const float* gin    = (const float*)d_in[19];
    const float* bein   = (const float*)d_in[20];
    const float* gsl    = (const float*)d_in[21];
    const float* besl   = (const float*)d_in[22];
    const float* gff    = (const float*)d_in[23];
    const float* beff   = (const float*)d_in[24];

    const int ATTN_SMEM = 5864 * 8;   // 46.9 KB -> 4 CTAs/SM
    static int configured = 0;
    if (!configured) {
        cudaFuncSetAttribute(attn_pass, cudaFuncAttributeMaxDynamicSharedMemorySize, ATTN_SMEM);
        cudaFuncSetAttribute(slot_begin, cudaFuncAttributeMaxDynamicSharedMemorySize, SLOT_SMEM);
        cudaFuncSetAttribute(slot_step, cudaFuncAttributeMaxDynamicSharedMemorySize, SLOT_SMEM);
        configured = 1;
    }

    slot_begin<<<64, 512, SLOT_SMEM>>>(noise, mu, sigma, Wq, bq, Wk, bk,
                                       gsl, besl, gin, bein);
    for (int it = 0; it < 3; it++) {
        attn_pass<<<1024, 128, ATTN_SMEM>>>(inputs);
        slot_step<<<64, 512, SLOT_SMEM>>>(Wv, bv, W_ih, W_hh, b_ih, b_hh,
                                          W1, b1, W2, b2, gin, bein, gff, beff,
                                          Wq, bq, Wk, bk, gsl, besl,
                                          it == 2 ? (float*)d_out : nullptr,
                                          it == 2 ? 0 : 1);
    }
}

// round 14
// speedup vs baseline: 1.0689x; 1.0533x over previous
#include <cuda_runtime.h>
#include <math.h>
#include <stdint.h>
typedef unsigned long long ull;

#define SCALE 0.125f
#define EPSA 1e-8f
#define LN_EPS 1e-5f

__device__ __forceinline__ ull fma2(ull a, ull b, ull c){ull d;asm("fma.rn.f32x2 %0,%1,%2,%3;":"=l"(d):"l"(a),"l"(b),"l"(c));return d;}
__device__ __forceinline__ ull add2(ull a, ull b){ull d;asm("add.rn.f32x2 %0,%1,%2;":"=l"(d):"l"(a),"l"(b));return d;}
__device__ __forceinline__ ull pack2(float lo, float hi){ull d;asm("mov.b64 %0,{%1,%2};":"=l"(d):"f"(lo),"f"(hi));return d;}
__device__ __forceinline__ void unpack2(ull v, float& lo, float& hi){asm("mov.b64 {%0,%1},%2;":"=f"(lo),"=f"(hi):"l"(v));}

__device__ __forceinline__ uint32_t smem_u32(const void* p){
    uint32_t a; asm("{.reg .u64 t; cvta.to.shared.u64 t, %1; cvt.u32.u64 %0, t;}" : "=r"(a) : "l"(p)); return a;
}
__device__ __forceinline__ void bulk_cp(uint32_t dst, const void* src, uint32_t bytes, uint32_t mbar){
    asm volatile("cp.async.bulk.shared::cta.global.mbarrier::complete_tx::bytes [%0], [%1], %2, [%3];"
                 :: "r"(dst), "l"(src), "r"(bytes), "r"(mbar) : "memory");
}
__device__ __forceinline__ void mbar_init(uint32_t mbar, uint32_t cnt){
    asm volatile("mbarrier.init.shared.b64 [%0], %1;" :: "r"(mbar), "r"(cnt) : "memory");
}
__device__ __forceinline__ void mbar_expect(uint32_t mbar, uint32_t bytes){
    asm volatile("mbarrier.arrive.expect_tx.shared.b64 _, [%0], %1;" :: "r"(mbar), "r"(bytes) : "memory");
}
__device__ __forceinline__ void mbar_waitp(uint32_t mbar, uint32_t parity){
    uint32_t done;
    do {
        asm volatile("{\n\t.reg .pred p;\n\t"
                     "mbarrier.try_wait.parity.acquire.cta.shared::cta.b64 p, [%1], %2;\n\t"
                     "selp.b32 %0, 1, 0, p;\n\t}"
                     : "=r"(done) : "r"(mbar), "r"(parity) : "memory");
    } while (!done);
}

// device scratch
__device__ float g_slots[64*448];
__device__ ull   g_ug2[64*224];     // pairs of SCALE*u*g_in
__device__ ull   g_ub2[64*7];       // {ub, Su}
__device__ ull   g_P2[1024*224];    // per (b,chunk16) raw-x weighted sums
__device__ ull   g_KD2[1024*7];     // per (b,chunk16) {K, D}

// ---------------------------------------------------------------------------
// attn_pass (exact R10 config, best measured 31.0-31.2us):
// grid 1024 = 64 b x 16 chunks of 256 tokens (2 passes x 128).
// ---------------------------------------------------------------------------
__global__ void __launch_bounds__(128,4) attn_pass(const float* __restrict__ inp)
{
    extern __shared__ ull sm[];
    ull* Xs = sm;            // [128][34]
    ull* As = sm + 4352;     // [128][10]
    ull* Ub = sm + 5632;     // [7] (+1 pad)
    ull* Ug = sm + 5640;     // [7][32]

    int tid = threadIdx.x, blk = blockIdx.x;
    int b = blk >> 4, chunk = blk & 15;

    for (int i = tid; i < 224; i += 128) Ug[i] = g_ug2[b*224 + i];
    if (tid < 7) Ub[tid] = g_ub2[b*7 + tid];

    ull p2[7]; ull kd2 = 0ull;
    #pragma unroll
    for (int i = 0; i < 7; i++) p2[i] = 0ull;

    const ulonglong2* in4 = (const ulonglong2*)inp + (size_t)(b*4096 + chunk*256)*16;
    int w8 = tid >> 5, cp = tid & 31;

    for (int pass = 0; pass < 2; pass++) {
        __syncthreads();
        const ulonglong2* src = in4 + pass*128*16;
        #pragma unroll
        for (int k = 0; k < 16; k++) {
            int idx = tid + k*128;
            int t = idx >> 4, c = idx & 15;
            ulonglong2 v = src[idx];
            *reinterpret_cast<ulonglong2*>(Xs + t*34 + c*2) = v;
        }
        __syncthreads();
        {
            ull* xrow = Xs + tid*34;
            ull sa = 0ull, qa = 0ull, acc[7];
            #pragma unroll
            for (int i = 0; i < 7; i++) acc[i] = 0ull;
            #pragma unroll
            for (int q2 = 0; q2 < 16; q2++) {
                ulonglong2 xv = *reinterpret_cast<const ulonglong2*>(xrow + q2*2);
                sa = add2(add2(sa, xv.x), xv.y);
                qa = fma2(xv.y, xv.y, fma2(xv.x, xv.x, qa));
                #pragma unroll
                for (int i = 0; i < 7; i++) {
                    ulonglong2 u = *reinterpret_cast<const ulonglong2*>(Ug + i*32 + q2*2);
                    acc[i] = fma2(xv.y, u.y, fma2(xv.x, u.x, acc[i]));
                }
            }
            float s0,s1,q0,q1; unpack2(sa,s0,s1); unpack2(qa,q0,q1);
            float m    = (s0 + s1) * 0.015625f;
            float varr = fmaf(-m, m, (q0 + q1) * 0.015625f) + LN_EPS;
            float inv  = rsqrtf(varr);
            float stdv = varr * inv;
            float d[7];
            #pragma unroll
            for (int i = 0; i < 7; i++) {
                float a0,a1,ub,su;
                unpack2(acc[i], a0, a1);
                unpack2(Ub[i], ub, su);
                d[i] = fmaf(fmaf(-m, su, a0 + a1), inv, ub);
            }
            float mx = d[0];
            #pragma unroll
            for (int i = 1; i < 7; i++) mx = fmaxf(mx, d[i]);
            float e[7], se = 0.f;
            #pragma unroll
            for (int i = 0; i < 7; i++) { e[i] = __expf(d[i] - mx); se += e[i]; }
            float rinv = 1.0f / se;
            float wv[7];
            #pragma unroll
            for (int i = 0; i < 7; i++) wv[i] = fmaf(e[i], rinv, EPSA) * inv;
            ull* arow = As + tid*10;
            *reinterpret_cast<ulonglong2*>(arow + 0) =
                make_ulonglong2(pack2(wv[0],wv[0]), pack2(wv[1],wv[1]));
            *reinterpret_cast<ulonglong2*>(arow + 2) =
                make_ulonglong2(pack2(wv[2],wv[2]), pack2(wv[3],wv[3]));
            *reinterpret_cast<ulonglong2*>(arow + 4) =
                make_ulonglong2(pack2(wv[4],wv[4]), pack2(wv[5],wv[5]));
            *reinterpret_cast<ulonglong2*>(arow + 6) =
                make_ulonglong2(pack2(wv[6],wv[6]), pack2(wv[6],wv[6]));
            xrow[32] = pack2(m, stdv);
        }
        __syncthreads();
        {
            int tb = w8 * 32;
            #pragma unroll 4
            for (int j = 0; j < 32; j++) {
                int t = tb + j;
                ull xv = Xs[t*34 + cp];
                const ulonglong2* ap = reinterpret_cast<const ulonglong2*>(As + t*10);
                ulonglong2 a01 = ap[0], a23 = ap[1], a45 = ap[2];
                ull a6 = As[t*10 + 6];
                p2[0] = fma2(a01.x, xv, p2[0]);
                p2[1] = fma2(a01.y, xv, p2[1]);
                p2[2] = fma2(a23.x, xv, p2[2]);
                p2[3] = fma2(a23.y, xv, p2[3]);
                p2[4] = fma2(a45.x, xv, p2[4]);
                p2[5] = fma2(a45.y, xv, p2[5]);
                p2[6] = fma2(a6,    xv, p2[6]);
            }
        }
        if (tid < 112) {
            int i = tid >> 4, tg = tid & 15;
            #pragma unroll
            for (int j = 0; j < 8; j++) {
                int t = j*16 + tg;
                kd2 = fma2(As[t*10 + i], Xs[t*34 + 32], kd2);
            }
        }
    }
    __syncthreads();
    #pragma unroll
    for (int i = 0; i < 7; i++) Xs[w8*224 + i*32 + cp] = p2[i];
    ull* redKD = Xs + 896;
    if (tid < 112) redKD[tid] = kd2;
    __syncthreads();
    for (int o = tid; o < 224; o += 128) {
        ull s = 0ull;
        #pragma unroll
        for (int h = 0; h < 4; h++) s = add2(s, Xs[h*224 + o]);
        g_P2[blk*224 + o] = s;
    }
    if (tid >= 112 && tid < 119) {
        int i = tid - 112;
        ull s = 0ull;
        #pragma unroll
        for (int tg = 0; tg < 16; tg++) s = add2(s, redKD[i*16 + tg]);
        g_KD2[blk*7 + i] = s;
    }
}

// ---------------------------------------------------------------------------
// slot-side: weights bulk-copied RAW; weight-shared GRU/P6 remaps.
// ---------------------------------------------------------------------------
#define OWQ   0        // 64x64
#define OWK   4096     // 64x64
#define OWV   8192     // 64x64
#define OWIH  12288    // 192x64
#define OWHH  24576    // 192x64
#define OW1   36864    // 128x64
#define OW2   45056    // 64x128 (phase-B copy; GRU scratch overlays earlier)
#define OXA   53248    // 448: sxa / sff / P6 partial scratch / prep-sS
#define OUPD  53696    // 448: supd / P6 scratch tail / prep-sQ
#define OH    54144    // 448: h / new slots
#define ONEW  54592    // 448
#define OY1   55040    // 896: y1 / prep-sU
#define SLOT_SMEM (55936*4)

__device__ __forceinline__ void warp_ln(const float* src, float* dst,
                                        const float* __restrict__ g,
                                        const float* __restrict__ be,
                                        int w, int lane) {
    float v0 = src[w*64 + lane], v1 = src[w*64 + 32 + lane];
    float s = v0 + v1, ss = v0*v0 + v1*v1;
    #pragma unroll
    for (int o = 16; o; o >>= 1) {
        s  += __shfl_xor_sync(0xffffffffu, s,  o);
        ss += __shfl_xor_sync(0xffffffffu, ss, o);
    }
    float m   = s * 0.015625f;
    float inv = rsqrtf(ss * 0.015625f - m*m + LN_EPS);
    dst[w*64 + lane]      = (v0 - m)*inv*g[lane]      + be[lane];
    dst[w*64 + 32 + lane] = (v1 - m)*inv*g[lane + 32] + be[lane + 32];
}

__device__ __forceinline__ float rotdot64(const float* Wrow, const float* v, int c) {
    float a0 = 0.f, a1 = 0.f;
    #pragma unroll 8
    for (int s = 0; s < 64; s += 2) {
        int d0 = (c + s) & 63, d1 = (c + s + 1) & 63;
        a0 = fmaf(Wrow[d0], v[d0], a0);
        a1 = fmaf(Wrow[d1], v[d1], a1);
    }
    return a0 + a1;
}

__device__ void do_prep(int b, int tid, float* fs,
                        const float* __restrict__ bq, const float* __restrict__ bk,
                        const float* __restrict__ gsl, const float* __restrict__ besl,
                        const float* __restrict__ gin, const float* __restrict__ bein)
{
    float* sS = fs + OXA;
    float* sQ = fs + OUPD;
    float* sU = fs + OY1;
    int w = tid >> 5, lane = tid & 31;
    if (w < 7) warp_ln(fs + OH, sS, gsl, besl, w, lane);
    __syncthreads();
    if (tid < 448) {
        int i = tid >> 6, c = tid & 63;
        sQ[tid] = bq[c] + rotdot64(fs + OWQ + c*64, sS + i*64, c);
    }
    __syncthreads();
    if (tid < 448) {
        int i = tid >> 6, e = tid & 63;
        float a0 = 0.f, a1 = 0.f;
        #pragma unroll 8
        for (int c = 0; c < 64; c += 2) {
            a0 = fmaf(sQ[i*64 + c],   fs[OWK + c*64 + e],     a0);
            a1 = fmaf(sQ[i*64 + c+1], fs[OWK + (c+1)*64 + e], a1);
        }
        float u = a0 + a1;
        sU[tid] = u;
        ((float*)g_ug2)[b*448 + tid] = u * gin[e] * SCALE;
    }
    __syncthreads();
    if (w < 7) {
        float u0 = sU[w*64 + lane], u1 = sU[w*64 + 32 + lane];
        float su = u0*gin[lane]  + u1*gin[lane + 32];
        float ub = u0*bein[lane] + u1*bein[lane + 32]
                 + sQ[w*64 + lane]*bk[lane] + sQ[w*64 + 32 + lane]*bk[lane + 32];
        #pragma unroll
        for (int o = 16; o; o >>= 1) {
            su += __shfl_xor_sync(0xffffffffu, su, o);
            ub += __shfl_xor_sync(0xffffffffu, ub, o);
        }
        if (lane == 0) g_ub2[b*7 + w] = pack2(SCALE*ub, SCALE*su);
    }
}

__global__ void __launch_bounds__(512,1)
slot_begin(const float* __restrict__ noise, const float* __restrict__ mu,
           const float* __restrict__ sigma,
           const float* __restrict__ Wq, const float* __restrict__ bq,
           const float* __restrict__ Wk, const float* __restrict__ bk,
           const float* __restrict__ gsl, const float* __restrict__ besl,
           const float* __restrict__ gin, const float* __restrict__ bein)
{
    extern __shared__ float fs[];
    __shared__ ull mbar_s;
    int b = blockIdx.x, tid = threadIdx.x;
    uint32_t sbase = smem_u32(fs);
    uint32_t mbar  = smem_u32(&mbar_s);
    if (tid == 0) mbar_init(mbar, 1);
    __syncthreads();
    if (tid == 0) {
        mbar_expect(mbar, 2*16384);
        bulk_cp(sbase + OWQ*4, Wq, 16384, mbar);
        bulk_cp(sbase + OWK*4, Wk, 16384, mbar);
    }
    if (tid < 448) {
        int c = tid & 63;
        float v = fmaf(sigma[c], noise[b*448 + tid], mu[c]);
        g_slots[b*448 + tid] = v;
        fs[OH + tid] = v;
    }
    __syncthreads();
    mbar_waitp(mbar, 0);
    do_prep(b, tid, fs, bq, bk, gsl, besl, gin, bein);
}

__global__ void __launch_bounds__(512,1)
slot_step(const float* __restrict__ Wv, const float* __restrict__ bv,
          const float* __restrict__ W_ih, const float* __restrict__ W_hh,
          const float* __restrict__ b_ih, const float* __restrict__ b_hh,
          const float* __restrict__ W1, const float* __restrict__ b1,
          const float* __restrict__ W2, const float* __restrict__ b2,
          const float* __restrict__ gin, const float* __restrict__ bein,
          const float* __restrict__ gff, const float* __restrict__ beff,
          const float* __restrict__ Wq, const float* __restrict__ bq,
          const float* __restrict__ Wk, const float* __restrict__ bk,
          const float* __restrict__ gsl, const float* __restrict__ besl,
          float* __restrict__ outp, int doprep)
{
    extern __shared__ float fs[];
    __shared__ ull mbar_s;
    __shared__ float sK[7], sD[7];
    float* sxa  = fs + OXA;
    float* supd = fs + OUPD;
    float* sh   = fs + OH;
    float* snew = fs + ONEW;
    float* sff  = fs + OXA;
    float* sy1  = fs + OY1;
    int b = blockIdx.x, tid = threadIdx.x;
    int w = tid >> 5, lane = tid & 31;
    const float* gP = (const float*)g_P2;
    uint32_t sbase = smem_u32(fs);
    uint32_t mbar  = smem_u32(&mbar_s);

    if (tid == 0) mbar_init(mbar, 1);
    __syncthreads();
    // Phase A: everything except W2 (its region doubles as GRU scratch)
    if (tid == 0) {
        uint32_t total = 16384 + 2*49152 + 32768 + (doprep ? 2*16384 : 0);
        mbar_expect(mbar, total);
        bulk_cp(sbase + OWV*4,  Wv,   16384, mbar);
        bulk_cp(sbase + OWIH*4, W_ih, 49152, mbar);
        bulk_cp(sbase + OWHH*4, W_hh, 49152, mbar);
        bulk_cp(sbase + OW1*4,  W1,   32768, mbar);
        if (doprep) {
            bulk_cp(sbase + OWQ*4, Wq, 16384, mbar);
            bulk_cp(sbase + OWK*4, Wk, 16384, mbar);
        }
    }

    // P0: reduce partials (16 chunks; overlaps bulk copies)
    if (tid < 448) {
        float s = 0.f;
        #pragma unroll
        for (int ch = 0; ch < 16; ch++) s += gP[(b*16 + ch)*448 + tid];
        sxa[tid] = s;
        sh[tid]  = g_slots[b*448 + tid];
    }
    if (tid < 7) {
        float K = 0.f, D = 0.f;
        #pragma unroll
        for (int ch = 0; ch < 16; ch++) {
            float k0, d0; unpack2(g_KD2[(b*16 + ch)*7 + tid], k0, d0);
            K += k0; D += d0;
        }
        sK[tid] = K; sD[tid] = D;
    }
    __syncthreads();
    // P1
    if (tid < 448) {
        int e = tid & 63, i = tid >> 6;
        sxa[tid] = fmaf((sxa[tid] - sK[i]) / sD[i], gin[e], bein[e]);
    }
    __syncthreads();
    mbar_waitp(mbar, 0);
    // P2: upd = xa @ Wv^T + bv
    if (tid < 448) {
        int c = tid & 63, i = tid >> 6;
        supd[tid] = bv[c] + rotdot64(fs + OWV + c*64, sxa + i*64, c);
    }
    __syncthreads();
    // P3a: GRU dot partials, weight-shared. thread (c, h) covers 32 d's for
    // all 7 slots x 6 gates. Scratch = OW2 region (W2 not yet copied).
    if (tid < 128) {
        int c = tid & 63, h = tid >> 6;
        const float* wir = fs + OWIH + c*64;
        const float* wiz = fs + OWIH + (64 + c)*64;
        const float* win = fs + OWIH + (128 + c)*64;
        const float* whr = fs + OWHH + c*64;
        const float* whz = fs + OWHH + (64 + c)*64;
        const float* whn = fs + OWHH + (128 + c)*64;
        float air[7], aiz[7], ain[7], ahr[7], ahz[7], ahn[7];
        #pragma unroll
        for (int i = 0; i < 7; i++) { air[i]=0.f; aiz[i]=0.f; ain[i]=0.f; ahr[i]=0.f; ahz[i]=0.f; ahn[i]=0.f; }
        int dbase = h * 32;
        #pragma unroll 4
        for (int s = 0; s < 32; s++) {
            int d = dbase + ((c + s) & 31);
            float wr_ = wir[d], wz_ = wiz[d], wn_ = win[d];
            float vr_ = whr[d], vz_ = whz[d], vn_ = whn[d];
            #pragma unroll
            for (int i = 0; i < 7; i++) {
                float xv = supd[i*64 + d];
                float hv = sh[i*64 + d];
                air[i] = fmaf(xv, wr_, air[i]);
                aiz[i] = fmaf(xv, wz_, aiz[i]);
                ain[i] = fmaf(xv, wn_, ain[i]);
                ahr[i] = fmaf(hv, vr_, ahr[i]);
                ahz[i] = fmaf(hv, vz_, ahz[i]);
                ahn[i] = fmaf(hv, vn_, ahn[i]);
            }
        }
        float* scr = fs + OW2 + tid*42;
        #pragma unroll
        for (int i = 0; i < 7; i++) {
            scr[i*6+0] = air[i]; scr[i*6+1] = aiz[i]; scr[i*6+2] = ain[i];
            scr[i*6+3] = ahr[i]; scr[i*6+4] = ahz[i]; scr[i*6+5] = ahn[i];
        }
    }
    __syncthreads();
    // P3b: combine halves + gates
    if (tid < 448) {
        int c = tid & 63, i = tid >> 6;
        const float* s0 = fs + OW2 + c*42 + i*6;
        const float* s1 = fs + OW2 + (64 + c)*42 + i*6;
        float gir = s0[0] + s1[0] + b_ih[c];
        float giz = s0[1] + s1[1] + b_ih[64 + c];
        float gin_ = s0[2] + s1[2] + b_ih[128 + c];
        float ghr = s0[3] + s1[3] + b_hh[c];
        float ghz = s0[4] + s1[4] + b_hh[64 + c];
        float ghn = s0[5] + s1[5] + b_hh[128 + c];
        float rg = 1.0f / (1.0f + __expf(-(gir + ghr)));
        float zg = 1.0f / (1.0f + __expf(-(giz + ghz)));
        float ng = tanhf(fmaf(rg, ghn, gin_));
        snew[tid] = fmaf(zg, sh[tid] - ng, ng);
    }
    __syncthreads();
    // Phase B: W2 copy (GRU scratch dead now)
    if (tid == 0) {
        mbar_expect(mbar, 32768);
        bulk_cp(sbase + OW2*4, W2, 32768, mbar);
    }
    // P4: LN(snew) -> sff
    if (w < 7) warp_ln(snew, sff, gff, beff, w, lane);
    __syncthreads();
    // P5: y1 = relu(ff @ W1^T + b1)
    for (int idx = tid; idx < 896; idx += 512) {
        int i = idx >> 7, r = idx & 127;
        const float* wr = fs + OW1 + r*64;
        const float* v  = sff + i*64;
        float a0 = 0.f, a1 = 0.f;
        #pragma unroll 8
        for (int s = 0; s < 64; s += 2) {
            int d0 = (r + s) & 63, d1 = (r + s + 1) & 63;
            a0 = fmaf(wr[d0], v[d0], a0);
            a1 = fmaf(wr[d1], v[d1], a1);
        }
        sy1[idx] = fmaxf(b1[r] + a0 + a1, 0.0f);
    }
    __syncthreads();
    mbar_waitp(mbar, 1);
    // P6a: W2 partials, weight-shared. thread (c, rh) covers 64 r's for 7 slots.
    // Scratch = OXA..OUPD (sxa/sff dead, supd dead).
    if (tid < 128) {
        int c = tid & 63, rh = tid >> 6;
        const float* wr = fs + OW2 + c*128;
        float a[7];
        #pragma unroll
        for (int i = 0; i < 7; i++) a[i] = 0.f;
        int rbase = rh * 64;
        #pragma unroll 4
        for (int s = 0; s < 64; s++) {
            int r = rbase + ((c + s) & 63);
            float wv = wr[r];
            #pragma unroll
            for (int i = 0; i < 7; i++)
                a[i] = fmaf(sy1[i*128 + r], wv, a[i]);
        }
        float* ps = fs + OXA + tid*7;
        #pragma unroll
        for (int i = 0; i < 7; i++) ps[i] = a[i];
    }
    __syncthreads();
    // P6b: combine + output
    if (tid < 448) {
        int c = tid & 63, i = tid >> 6;
        float a = fs[OXA + c*7 + i] + fs[OXA + (64 + c)*7 + i];
        float vout = snew[tid] + b2[c] + a;
        g_slots[b*448 + tid] = vout;
        sh[tid] = vout;
        if (outp) outp[b*448 + tid] = vout;
    }
    if (doprep) {
        __syncthreads();
        do_prep(b, tid, fs, bq, bk, gsl, besl, gin, bein);
    }
}

// ---------------------------------------------------------------------------
extern "C" void kernel_launch(void* const* d_in, const int* in_sizes, int n_in,
                              void* d_out, int out_size)
{
    const float* inputs = (const float*)d_in[0];
    const float* noise  = (const float*)d_in[2];
    const float* mu     = (const float*)d_in[3];
    const float* sigma  = (const float*)d_in[4];
    const float* Wq     = (const float*)d_in[5];
    const float* bq     = (const float*)d_in[6];
    const float* Wk     = (const float*)d_in[7];
    const float* bk     = (const float*)d_in[8];
    const float* Wv     = (const float*)d_in[9];
    const float* bv     = (const float*)d_in[10];
    const float* W_ih   = (const float*)d_in[11];
    const float* W_hh   = (const float*)d_in[12];
    const float* b_ih   = (const float*)d_in[13];
    const float* b_hh   = (const float*)d_in[14];
    const float* W1     = (const float*)d_in[15];
    const float* b1     = (const float*)d_in[16];
    const float* W2     = (const float*)d_in[17];
    const float* b2     = (const float*)d_in[18];
    const float* gin    = (const float*)d_in[19];
    const float* bein   = (const float*)d_in[20];
    const float* gsl    = (const float*)d_in[21];
    const float* besl   = (const float*)d_in[22];
    const float* gff    = (const float*)d_in[23];
    const float* beff   = (const float*)d_in[24];

    const int ATTN_SMEM = 5864 * 8;   // 46.9 KB -> 4 CTAs/SM
    static int configured = 0;
    if (!configured) {
        cudaFuncSetAttribute(attn_pass, cudaFuncAttributeMaxDynamicSharedMemorySize, ATTN_SMEM);
        cudaFuncSetAttribute(slot_begin, cudaFuncAttributeMaxDynamicSharedMemorySize, SLOT_SMEM);
        cudaFuncSetAttribute(slot_step, cudaFuncAttributeMaxDynamicSharedMemorySize, SLOT_SMEM);
        configured = 1;
    }

    slot_begin<<<64, 512, SLOT_SMEM>>>(noise, mu, sigma, Wq, bq, Wk, bk,
                                       gsl, besl, gin, bein);
    for (int it = 0; it < 3; it++) {
        attn_pass<<<1024, 128, ATTN_SMEM>>>(inputs);
        slot_step<<<64, 512, SLOT_SMEM>>>(Wv, bv, W_ih, W_hh, b_ih, b_hh,
                                          W1, b1, W2, b2, gin, bein, gff, beff,
                                          Wq, bq, Wk, bk, gsl, besl,
                                          it == 2 ? (float*)d_out : nullptr,
                                          it == 2 ? 0 : 1);
    }
}

// round 15
// speedup vs baseline: 1.1180x; 1.0459x over previous
#include <cuda_runtime.h>
#include <math.h>
#include <stdint.h>
typedef unsigned long long ull;

#define SCALE 0.125f
#define EPSA 1e-8f
#define LN_EPS 1e-5f

__device__ __forceinline__ ull fma2(ull a, ull b, ull c){ull d;asm("fma.rn.f32x2 %0,%1,%2,%3;":"=l"(d):"l"(a),"l"(b),"l"(c));return d;}
__device__ __forceinline__ ull add2(ull a, ull b){ull d;asm("add.rn.f32x2 %0,%1,%2;":"=l"(d):"l"(a),"l"(b));return d;}
__device__ __forceinline__ ull pack2(float lo, float hi){ull d;asm("mov.b64 %0,{%1,%2};":"=l"(d):"f"(lo),"f"(hi));return d;}
__device__ __forceinline__ void unpack2(ull v, float& lo, float& hi){asm("mov.b64 {%0,%1},%2;":"=f"(lo),"=f"(hi):"l"(v));}

__device__ __forceinline__ void pdl_trigger(){ asm volatile("griddepcontrol.launch_dependents;"); }
__device__ __forceinline__ void pdl_wait(){ asm volatile("griddepcontrol.wait;" ::: "memory"); }

__device__ __forceinline__ uint32_t smem_u32(const void* p){
    uint32_t a; asm("{.reg .u64 t; cvta.to.shared.u64 t, %1; cvt.u32.u64 %0, t;}" : "=r"(a) : "l"(p)); return a;
}
__device__ __forceinline__ void bulk_cp(uint32_t dst, const void* src, uint32_t bytes, uint32_t mbar){
    asm volatile("cp.async.bulk.shared::cta.global.mbarrier::complete_tx::bytes [%0], [%1], %2, [%3];"
                 :: "r"(dst), "l"(src), "r"(bytes), "r"(mbar) : "memory");
}
__device__ __forceinline__ void mbar_init(uint32_t mbar, uint32_t cnt){
    asm volatile("mbarrier.init.shared.b64 [%0], %1;" :: "r"(mbar), "r"(cnt) : "memory");
}
__device__ __forceinline__ void mbar_expect(uint32_t mbar, uint32_t bytes){
    asm volatile("mbarrier.arrive.expect_tx.shared.b64 _, [%0], %1;" :: "r"(mbar), "r"(bytes) : "memory");
}
__device__ __forceinline__ void mbar_waitp(uint32_t mbar, uint32_t parity){
    uint32_t done;
    do {
        asm volatile("{\n\t.reg .pred p;\n\t"
                     "mbarrier.try_wait.parity.acquire.cta.shared::cta.b64 p, [%1], %2;\n\t"
                     "selp.b32 %0, 1, 0, p;\n\t}"
                     : "=r"(done) : "r"(mbar), "r"(parity) : "memory");
    } while (!done);
}

// device scratch
__device__ float g_slots[64*448];
__device__ ull   g_ug2[64*224];     // pairs of SCALE*u*g_in
__device__ ull   g_ub2[64*7];       // {ub, Su}
__device__ ull   g_P2[1024*224];    // per (b,chunk16) raw-x weighted sums
__device__ ull   g_KD2[1024*7];     // per (b,chunk16) {K, D}

// ---------------------------------------------------------------------------
// attn_pass (R10 config + PDL): grid 1024 = 64 b x 16 chunks (2 passes x 128).
// Pass-0 input LDGs issue BEFORE griddepcontrol.wait (independent of slots).
// ---------------------------------------------------------------------------
__global__ void __launch_bounds__(128,4) attn_pass(const float* __restrict__ inp)
{
    extern __shared__ ull sm[];
    ull* Xs = sm;            // [128][34]
    ull* As = sm + 4352;     // [128][10]
    ull* Ub = sm + 5632;     // [7] (+1 pad)
    ull* Ug = sm + 5640;     // [7][32]

    int tid = threadIdx.x, blk = blockIdx.x;
    int b = blk >> 4, chunk = blk & 15;

    pdl_trigger();

    ull p2[7]; ull kd2 = 0ull;
    #pragma unroll
    for (int i = 0; i < 7; i++) p2[i] = 0ull;

    const ulonglong2* in4 = (const ulonglong2*)inp + (size_t)(b*4096 + chunk*256)*16;
    int w8 = tid >> 5, cp = tid & 31;

    for (int pass = 0; pass < 2; pass++) {
        __syncthreads();
        const ulonglong2* src = in4 + pass*128*16;
        #pragma unroll
        for (int k = 0; k < 16; k++) {
            int idx = tid + k*128;
            int t = idx >> 4, c = idx & 15;
            ulonglong2 v = src[idx];
            *reinterpret_cast<ulonglong2*>(Xs + t*34 + c*2) = v;
        }
        if (pass == 0) {
            // predecessor results needed only from here on
            pdl_wait();
            for (int i = tid; i < 224; i += 128) Ug[i] = g_ug2[b*224 + i];
            if (tid < 7) Ub[tid] = g_ub2[b*7 + tid];
        }
        __syncthreads();
        {
            ull* xrow = Xs + tid*34;
            ull sa = 0ull, qa = 0ull, acc[7];
            #pragma unroll
            for (int i = 0; i < 7; i++) acc[i] = 0ull;
            #pragma unroll
            for (int q2 = 0; q2 < 16; q2++) {
                ulonglong2 xv = *reinterpret_cast<const ulonglong2*>(xrow + q2*2);
                sa = add2(add2(sa, xv.x), xv.y);
                qa = fma2(xv.y, xv.y, fma2(xv.x, xv.x, qa));
                #pragma unroll
                for (int i = 0; i < 7; i++) {
                    ulonglong2 u = *reinterpret_cast<const ulonglong2*>(Ug + i*32 + q2*2);
                    acc[i] = fma2(xv.y, u.y, fma2(xv.x, u.x, acc[i]));
                }
            }
            float s0,s1,q0,q1; unpack2(sa,s0,s1); unpack2(qa,q0,q1);
            float m    = (s0 + s1) * 0.015625f;
            float varr = fmaf(-m, m, (q0 + q1) * 0.015625f) + LN_EPS;
            float inv  = rsqrtf(varr);
            float stdv = varr * inv;
            float d[7];
            #pragma unroll
            for (int i = 0; i < 7; i++) {
                float a0,a1,ub,su;
                unpack2(acc[i], a0, a1);
                unpack2(Ub[i], ub, su);
                d[i] = fmaf(fmaf(-m, su, a0 + a1), inv, ub);
            }
            float mx = d[0];
            #pragma unroll
            for (int i = 1; i < 7; i++) mx = fmaxf(mx, d[i]);
            float e[7], se = 0.f;
            #pragma unroll
            for (int i = 0; i < 7; i++) { e[i] = __expf(d[i] - mx); se += e[i]; }
            float rinv = 1.0f / se;
            float wv[7];
            #pragma unroll
            for (int i = 0; i < 7; i++) wv[i] = fmaf(e[i], rinv, EPSA) * inv;
            ull* arow = As + tid*10;
            *reinterpret_cast<ulonglong2*>(arow + 0) =
                make_ulonglong2(pack2(wv[0],wv[0]), pack2(wv[1],wv[1]));
            *reinterpret_cast<ulonglong2*>(arow + 2) =
                make_ulonglong2(pack2(wv[2],wv[2]), pack2(wv[3],wv[3]));
            *reinterpret_cast<ulonglong2*>(arow + 4) =
                make_ulonglong2(pack2(wv[4],wv[4]), pack2(wv[5],wv[5]));
            *reinterpret_cast<ulonglong2*>(arow + 6) =
                make_ulonglong2(pack2(wv[6],wv[6]), pack2(wv[6],wv[6]));
            xrow[32] = pack2(m, stdv);
        }
        __syncthreads();
        {
            int tb = w8 * 32;
            #pragma unroll 4
            for (int j = 0; j < 32; j++) {
                int t = tb + j;
                ull xv = Xs[t*34 + cp];
                const ulonglong2* ap = reinterpret_cast<const ulonglong2*>(As + t*10);
                ulonglong2 a01 = ap[0], a23 = ap[1], a45 = ap[2];
                ull a6 = As[t*10 + 6];
                p2[0] = fma2(a01.x, xv, p2[0]);
                p2[1] = fma2(a01.y, xv, p2[1]);
                p2[2] = fma2(a23.x, xv, p2[2]);
                p2[3] = fma2(a23.y, xv, p2[3]);
                p2[4] = fma2(a45.x, xv, p2[4]);
                p2[5] = fma2(a45.y, xv, p2[5]);
                p2[6] = fma2(a6,    xv, p2[6]);
            }
        }
        if (tid < 112) {
            int i = tid >> 4, tg = tid & 15;
            #pragma unroll
            for (int j = 0; j < 8; j++) {
                int t = j*16 + tg;
                kd2 = fma2(As[t*10 + i], Xs[t*34 + 32], kd2);
            }
        }
    }
    __syncthreads();
    #pragma unroll
    for (int i = 0; i < 7; i++) Xs[w8*224 + i*32 + cp] = p2[i];
    ull* redKD = Xs + 896;
    if (tid < 112) redKD[tid] = kd2;
    __syncthreads();
    for (int o = tid; o < 224; o += 128) {
        ull s = 0ull;
        #pragma unroll
        for (int h = 0; h < 4; h++) s = add2(s, Xs[h*224 + o]);
        g_P2[blk*224 + o] = s;
    }
    if (tid >= 112 && tid < 119) {
        int i = tid - 112;
        ull s = 0ull;
        #pragma unroll
        for (int tg = 0; tg < 16; tg++) s = add2(s, redKD[i*16 + tg]);
        g_KD2[blk*7 + i] = s;
    }
}

// ---------------------------------------------------------------------------
// slot-side (R14 config + PDL): weights bulk-copied RAW; weight-shared GRU/P6.
// ---------------------------------------------------------------------------
#define OWQ   0
#define OWK   4096
#define OWV   8192
#define OWIH  12288
#define OWHH  24576
#define OW1   36864
#define OW2   45056
#define OXA   53248
#define OUPD  53696
#define OH    54144
#define ONEW  54592
#define OY1   55040
#define SLOT_SMEM (55936*4)

__device__ __forceinline__ void warp_ln(const float* src, float* dst,
                                        const float* __restrict__ g,
                                        const float* __restrict__ be,
                                        int w, int lane) {
    float v0 = src[w*64 + lane], v1 = src[w*64 + 32 + lane];
    float s = v0 + v1, ss = v0*v0 + v1*v1;
    #pragma unroll
    for (int o = 16; o; o >>= 1) {
        s  += __shfl_xor_sync(0xffffffffu, s,  o);
        ss += __shfl_xor_sync(0xffffffffu, ss, o);
    }
    float m   = s * 0.015625f;
    float inv = rsqrtf(ss * 0.015625f - m*m + LN_EPS);
    dst[w*64 + lane]      = (v0 - m)*inv*g[lane]      + be[lane];
    dst[w*64 + 32 + lane] = (v1 - m)*inv*g[lane + 32] + be[lane + 32];
}

__device__ __forceinline__ float rotdot64(const float* Wrow, const float* v, int c) {
    float a0 = 0.f, a1 = 0.f;
    #pragma unroll 8
    for (int s = 0; s < 64; s += 2) {
        int d0 = (c + s) & 63, d1 = (c + s + 1) & 63;
        a0 = fmaf(Wrow[d0], v[d0], a0);
        a1 = fmaf(Wrow[d1], v[d1], a1);
    }
    return a0 + a1;
}

__device__ void do_prep(int b, int tid, float* fs,
                        const float* __restrict__ bq, const float* __restrict__ bk,
                        const float* __restrict__ gsl, const float* __restrict__ besl,
                        const float* __restrict__ gin, const float* __restrict__ bein)
{
    float* sS = fs + OXA;
    float* sQ = fs + OUPD;
    float* sU = fs + OY1;
    int w = tid >> 5, lane = tid & 31;
    if (w < 7) warp_ln(fs + OH, sS, gsl, besl, w, lane);
    __syncthreads();
    if (tid < 448) {
        int i = tid >> 6, c = tid & 63;
        sQ[tid] = bq[c] + rotdot64(fs + OWQ + c*64, sS + i*64, c);
    }
    __syncthreads();
    if (tid < 448) {
        int i = tid >> 6, e = tid & 63;
        float a0 = 0.f, a1 = 0.f;
        #pragma unroll 8
        for (int c = 0; c < 64; c += 2) {
            a0 = fmaf(sQ[i*64 + c],   fs[OWK + c*64 + e],     a0);
            a1 = fmaf(sQ[i*64 + c+1], fs[OWK + (c+1)*64 + e], a1);
        }
        float u = a0 + a1;
        sU[tid] = u;
        ((float*)g_ug2)[b*448 + tid] = u * gin[e] * SCALE;
    }
    __syncthreads();
    if (w < 7) {
        float u0 = sU[w*64 + lane], u1 = sU[w*64 + 32 + lane];
        float su = u0*gin[lane]  + u1*gin[lane + 32];
        float ub = u0*bein[lane] + u1*bein[lane + 32]
                 + sQ[w*64 + lane]*bk[lane] + sQ[w*64 + 32 + lane]*bk[lane + 32];
        #pragma unroll
        for (int o = 16; o; o >>= 1) {
            su += __shfl_xor_sync(0xffffffffu, su, o);
            ub += __shfl_xor_sync(0xffffffffu, ub, o);
        }
        if (lane == 0) g_ub2[b*7 + w] = pack2(SCALE*ub, SCALE*su);
    }
}

__global__ void __launch_bounds__(512,1)
slot_begin(const float* __restrict__ noise, const float* __restrict__ mu,
           const float* __restrict__ sigma,
           const float* __restrict__ Wq, const float* __restrict__ bq,
           const float* __restrict__ Wk, const float* __restrict__ bk,
           const float* __restrict__ gsl, const float* __restrict__ besl,
           const float* __restrict__ gin, const float* __restrict__ bein)
{
    extern __shared__ float fs[];
    __shared__ ull mbar_s;
    int b = blockIdx.x, tid = threadIdx.x;
    uint32_t sbase = smem_u32(fs);
    uint32_t mbar  = smem_u32(&mbar_s);
    pdl_trigger();
    if (tid == 0) mbar_init(mbar, 1);
    __syncthreads();
    if (tid == 0) {
        mbar_expect(mbar, 2*16384);
        bulk_cp(sbase + OWQ*4, Wq, 16384, mbar);
        bulk_cp(sbase + OWK*4, Wk, 16384, mbar);
    }
    if (tid < 448) {
        int c = tid & 63;
        float v = fmaf(sigma[c], noise[b*448 + tid], mu[c]);
        g_slots[b*448 + tid] = v;
        fs[OH + tid] = v;
    }
    __syncthreads();
    mbar_waitp(mbar, 0);
    do_prep(b, tid, fs, bq, bk, gsl, besl, gin, bein);
}

__global__ void __launch_bounds__(512,1)
slot_step(const float* __restrict__ Wv, const float* __restrict__ bv,
          const float* __restrict__ W_ih, const float* __restrict__ W_hh,
          const float* __restrict__ b_ih, const float* __restrict__ b_hh,
          const float* __restrict__ W1, const float* __restrict__ b1,
          const float* __restrict__ W2, const float* __restrict__ b2,
          const float* __restrict__ gin, const float* __restrict__ bein,
          const float* __restrict__ gff, const float* __restrict__ beff,
          const float* __restrict__ Wq, const float* __restrict__ bq,
          const float* __restrict__ Wk, const float* __restrict__ bk,
          const float* __restrict__ gsl, const float* __restrict__ besl,
          float* __restrict__ outp, int doprep)
{
    extern __shared__ float fs[];
    __shared__ ull mbar_s;
    __shared__ float sK[7], sD[7];
    float* sxa  = fs + OXA;
    float* supd = fs + OUPD;
    float* sh   = fs + OH;
    float* snew = fs + ONEW;
    float* sff  = fs + OXA;
    float* sy1  = fs + OY1;
    int b = blockIdx.x, tid = threadIdx.x;
    int w = tid >> 5, lane = tid & 31;
    const float* gP = (const float*)g_P2;
    uint32_t sbase = smem_u32(fs);
    uint32_t mbar  = smem_u32(&mbar_s);

    pdl_trigger();
    if (tid == 0) mbar_init(mbar, 1);
    __syncthreads();
    // Phase A: everything except W2 (its region doubles as GRU scratch)
    if (tid == 0) {
        uint32_t total = 16384 + 2*49152 + 32768 + (doprep ? 2*16384 : 0);
        mbar_expect(mbar, total);
        bulk_cp(sbase + OWV*4,  Wv,   16384, mbar);
        bulk_cp(sbase + OWIH*4, W_ih, 49152, mbar);
        bulk_cp(sbase + OWHH*4, W_hh, 49152, mbar);
        bulk_cp(sbase + OW1*4,  W1,   32768, mbar);
        if (doprep) {
            bulk_cp(sbase + OWQ*4, Wq, 16384, mbar);
            bulk_cp(sbase + OWK*4, Wk, 16384, mbar);
        }
    }

    // predecessor (attn) results needed from here
    pdl_wait();
    // P0: reduce partials (16 chunks; overlaps bulk copies)
    if (tid < 448) {
        float s = 0.f;
        #pragma unroll
        for (int ch = 0; ch < 16; ch++) s += gP[(b*16 + ch)*448 + tid];
        sxa[tid] = s;
        sh[tid]  = g_slots[b*448 + tid];
    }
    if (tid < 7) {
        float K = 0.f, D = 0.f;
        #pragma unroll
        for (int ch = 0; ch < 16; ch++) {
            float k0, d0; unpack2(g_KD2[(b*16 + ch)*7 + tid], k0, d0);
            K += k0; D += d0;
        }
        sK[tid] = K; sD[tid] = D;
    }
    __syncthreads();
    // P1
    if (tid < 448) {
        int e = tid & 63, i = tid >> 6;
        sxa[tid] = fmaf((sxa[tid] - sK[i]) / sD[i], gin[e], bein[e]);
    }
    __syncthreads();
    mbar_waitp(mbar, 0);
    // P2: upd = xa @ Wv^T + bv
    if (tid < 448) {
        int c = tid & 63, i = tid >> 6;
        supd[tid] = bv[c] + rotdot64(fs + OWV + c*64, sxa + i*64, c);
    }
    __syncthreads();
    // P3a: GRU dot partials, weight-shared (scratch = OW2 region)
    if (tid < 128) {
        int c = tid & 63, h = tid >> 6;
        const float* wir = fs + OWIH + c*64;
        const float* wiz = fs + OWIH + (64 + c)*64;
        const float* win = fs + OWIH + (128 + c)*64;
        const float* whr = fs + OWHH + c*64;
        const float* whz = fs + OWHH + (64 + c)*64;
        const float* whn = fs + OWHH + (128 + c)*64;
        float air[7], aiz[7], ain[7], ahr[7], ahz[7], ahn[7];
        #pragma unroll
        for (int i = 0; i < 7; i++) { air[i]=0.f; aiz[i]=0.f; ain[i]=0.f; ahr[i]=0.f; ahz[i]=0.f; ahn[i]=0.f; }
        int dbase = h * 32;
        #pragma unroll 4
        for (int s = 0; s < 32; s++) {
            int d = dbase + ((c + s) & 31);
            float wr_ = wir[d], wz_ = wiz[d], wn_ = win[d];
            float vr_ = whr[d], vz_ = whz[d], vn_ = whn[d];
            #pragma unroll
            for (int i = 0; i < 7; i++) {
                float xv = supd[i*64 + d];
                float hv = sh[i*64 + d];
                air[i] = fmaf(xv, wr_, air[i]);
                aiz[i] = fmaf(xv, wz_, aiz[i]);
                ain[i] = fmaf(xv, wn_, ain[i]);
                ahr[i] = fmaf(hv, vr_, ahr[i]);
                ahz[i] = fmaf(hv, vz_, ahz[i]);
                ahn[i] = fmaf(hv, vn_, ahn[i]);
            }
        }
        float* scr = fs + OW2 + tid*42;
        #pragma unroll
        for (int i = 0; i < 7; i++) {
            scr[i*6+0] = air[i]; scr[i*6+1] = aiz[i]; scr[i*6+2] = ain[i];
            scr[i*6+3] = ahr[i]; scr[i*6+4] = ahz[i]; scr[i*6+5] = ahn[i];
        }
    }
    __syncthreads();
    // P3b: combine halves + gates
    if (tid < 448) {
        int c = tid & 63, i = tid >> 6;
        const float* s0 = fs + OW2 + c*42 + i*6;
        const float* s1 = fs + OW2 + (64 + c)*42 + i*6;
        float gir = s0[0] + s1[0] + b_ih[c];
        float giz = s0[1] + s1[1] + b_ih[64 + c];
        float gin_ = s0[2] + s1[2] + b_ih[128 + c];
        float ghr = s0[3] + s1[3] + b_hh[c];
        float ghz = s0[4] + s1[4] + b_hh[64 + c];
        float ghn = s0[5] + s1[5] + b_hh[128 + c];
        float rg = 1.0f / (1.0f + __expf(-(gir + ghr)));
        float zg = 1.0f / (1.0f + __expf(-(giz + ghz)));
        float ng = tanhf(fmaf(rg, ghn, gin_));
        snew[tid] = fmaf(zg, sh[tid] - ng, ng);
    }
    __syncthreads();
    // Phase B: W2 copy (GRU scratch dead now)
    if (tid == 0) {
        mbar_expect(mbar, 32768);
        bulk_cp(sbase + OW2*4, W2, 32768, mbar);
    }
    // P4: LN(snew) -> sff
    if (w < 7) warp_ln(snew, sff, gff, beff, w, lane);
    __syncthreads();
    // P5: y1 = relu(ff @ W1^T + b1)
    for (int idx = tid; idx < 896; idx += 512) {
        int i = idx >> 7, r = idx & 127;
        const float* wr = fs + OW1 + r*64;
        const float* v  = sff + i*64;
        float a0 = 0.f, a1 = 0.f;
        #pragma unroll 8
        for (int s = 0; s < 64; s += 2) {
            int d0 = (r + s) & 63, d1 = (r + s + 1) & 63;
            a0 = fmaf(wr[d0], v[d0], a0);
            a1 = fmaf(wr[d1], v[d1], a1);
        }
        sy1[idx] = fmaxf(b1[r] + a0 + a1, 0.0f);
    }
    __syncthreads();
    mbar_waitp(mbar, 1);
    // P6a: W2 partials, weight-shared (scratch = OXA..OUPD)
    if (tid < 128) {
        int c = tid & 63, rh = tid >> 6;
        const float* wr = fs + OW2 + c*128;
        float a[7];
        #pragma unroll
        for (int i = 0; i < 7; i++) a[i] = 0.f;
        int rbase = rh * 64;
        #pragma unroll 4
        for (int s = 0; s < 64; s++) {
            int r = rbase + ((c + s) & 63);
            float wv = wr[r];
            #pragma unroll
            for (int i = 0; i < 7; i++)
                a[i] = fmaf(sy1[i*128 + r], wv, a[i]);
        }
        float* ps = fs + OXA + tid*7;
        #pragma unroll
        for (int i = 0; i < 7; i++) ps[i] = a[i];
    }
    __syncthreads();
    // P6b: combine + output
    if (tid < 448) {
        int c = tid & 63, i = tid >> 6;
        float a = fs[OXA + c*7 + i] + fs[OXA + (64 + c)*7 + i];
        float vout = snew[tid] + b2[c] + a;
        g_slots[b*448 + tid] = vout;
        sh[tid] = vout;
        if (outp) outp[b*448 + tid] = vout;
    }
    if (doprep) {
        __syncthreads();
        do_prep(b, tid, fs, bq, bk, gsl, besl, gin, bein);
    }
}

// ---------------------------------------------------------------------------
extern "C" void kernel_launch(void* const* d_in, const int* in_sizes, int n_in,
                              void* d_out, int out_size)
{
    const float* inputs = (const float*)d_in[0];
    const float* noise  = (const float*)d_in[2];
    const float* mu     = (const float*)d_in[3];
    const float* sigma  = (const float*)d_in[4];
    const float* Wq     = (const float*)d_in[5];
    const float* bq     = (const float*)d_in[6];
    const float* Wk     = (const float*)d_in[7];
    const float* bk     = (const float*)d_in[8];
    const float* Wv     = (const float*)d_in[9];
    const float* bv     = (const float*)d_in[10];
    const float* W_ih   = (const float*)d_in[11];
    const float* W_hh   = (const float*)d_in[12];
    const float* b_ih   = (const float*)d_in[13];
    const float* b_hh   = (const float*)d_in[14];
    const float* W1     = (const float*)d_in[15];
    const float* b1     = (const float*)d_in[16];
    const float* W2     = (const float*)d_in[17];
    const float* b2     = (const float*)d_in[18];
    const float* gin    = (const float*)d_in[19];
    const float* bein   = (const float*)d_in[20];
    const float* gsl    = (const float*)d_in[21];
    const float* besl   = (const float*)d_in[22];
    const float* gff    = (const float*)d_in[23];
    const float* beff   = (const float*)d_in[24];

    const int ATTN_SMEM = 5864 * 8;
    static int configured = 0;
    if (!configured) {
        cudaFuncSetAttribute(attn_pass, cudaFuncAttributeMaxDynamicSharedMemorySize, ATTN_SMEM);
        cudaFuncSetAttribute(slot_begin, cudaFuncAttributeMaxDynamicSharedMemorySize, SLOT_SMEM);
        cudaFuncSetAttribute(slot_step, cudaFuncAttributeMaxDynamicSharedMemorySize, SLOT_SMEM);
        configured = 1;
    }

    cudaLaunchAttribute pdlAttr[1];
    pdlAttr[0].id = cudaLaunchAttributeProgrammaticStreamSerialization;
    pdlAttr[0].val.programmaticStreamSerializationAllowed = 1;

    // slot_begin (no PDL needed on the first launch)
    {
        cudaLaunchConfig_t cfg = {};
        cfg.gridDim = dim3(64,1,1); cfg.blockDim = dim3(512,1,1);
        cfg.dynamicSmemBytes = SLOT_SMEM;
        cudaLaunchKernelEx(&cfg, slot_begin, noise, mu, sigma, Wq, bq, Wk, bk,
                           gsl, besl, gin, bein);
    }
    for (int it = 0; it < 3; it++) {
        {
            cudaLaunchConfig_t cfg = {};
            cfg.gridDim = dim3(1024,1,1); cfg.blockDim = dim3(128,1,1);
            cfg.dynamicSmemBytes = ATTN_SMEM;
            cfg.attrs = pdlAttr; cfg.numAttrs = 1;
            cudaLaunchKernelEx(&cfg, attn_pass, inputs);
        }
        {
            cudaLaunchConfig_t cfg = {};
            cfg.gridDim = dim3(64,1,1); cfg.blockDim = dim3(512,1,1);
            cfg.dynamicSmemBytes = SLOT_SMEM;
            cfg.attrs = pdlAttr; cfg.numAttrs = 1;
            cudaLaunchKernelEx(&cfg, slot_step, Wv, bv, W_ih, W_hh, b_ih, b_hh,
                               W1, b1, W2, b2, gin, bein, gff, beff,
                               Wq, bq, Wk, bk, gsl, besl,
                               it == 2 ? (float*)d_out : (float*)nullptr,
                               it == 2 ? 0 : 1);
        }
    }
}

// round 16
// speedup vs baseline: 1.1197x; 1.0016x over previous
#include <cuda_runtime.h>
#include <math.h>
#include <stdint.h>
typedef unsigned long long ull;

#define SCALE 0.125f
#define EPSA 1e-8f
#define LN_EPS 1e-5f

__device__ __forceinline__ ull fma2(ull a, ull b, ull c){ull d;asm("fma.rn.f32x2 %0,%1,%2,%3;":"=l"(d):"l"(a),"l"(b),"l"(c));return d;}
__device__ __forceinline__ ull add2(ull a, ull b){ull d;asm("add.rn.f32x2 %0,%1,%2;":"=l"(d):"l"(a),"l"(b));return d;}
__device__ __forceinline__ ull pack2(float lo, float hi){ull d;asm("mov.b64 %0,{%1,%2};":"=l"(d):"f"(lo),"f"(hi));return d;}
__device__ __forceinline__ void unpack2(ull v, float& lo, float& hi){asm("mov.b64 {%0,%1},%2;":"=f"(lo),"=f"(hi):"l"(v));}

__device__ __forceinline__ void pdl_trigger(){ asm volatile("griddepcontrol.launch_dependents;"); }
__device__ __forceinline__ void pdl_wait(){ asm volatile("griddepcontrol.wait;" ::: "memory"); }

__device__ __forceinline__ uint32_t smem_u32(const void* p){
    uint32_t a; asm("{.reg .u64 t; cvta.to.shared.u64 t, %1; cvt.u32.u64 %0, t;}" : "=r"(a) : "l"(p)); return a;
}
__device__ __forceinline__ void bulk_cp(uint32_t dst, const void* src, uint32_t bytes, uint32_t mbar){
    asm volatile("cp.async.bulk.shared::cta.global.mbarrier::complete_tx::bytes [%0], [%1], %2, [%3];"
                 :: "r"(dst), "l"(src), "r"(bytes), "r"(mbar) : "memory");
}
__device__ __forceinline__ void mbar_init(uint32_t mbar, uint32_t cnt){
    asm volatile("mbarrier.init.shared.b64 [%0], %1;" :: "r"(mbar), "r"(cnt) : "memory");
}
__device__ __forceinline__ void mbar_expect(uint32_t mbar, uint32_t bytes){
    asm volatile("mbarrier.arrive.expect_tx.shared.b64 _, [%0], %1;" :: "r"(mbar), "r"(bytes) : "memory");
}
__device__ __forceinline__ void mbar_waitp(uint32_t mbar, uint32_t parity){
    uint32_t done;
    do {
        asm volatile("{\n\t.reg .pred p;\n\t"
                     "mbarrier.try_wait.parity.acquire.cta.shared::cta.b64 p, [%1], %2;\n\t"
                     "selp.b32 %0, 1, 0, p;\n\t}"
                     : "=r"(done) : "r"(mbar), "r"(parity) : "memory");
    } while (!done);
}

// device scratch
__device__ float g_slots[64*448];
__device__ ull   g_ug2[64*224];     // pairs of SCALE*u*g_in
__device__ ull   g_ub2[64*7];       // {ub, Su}
__device__ ull   g_P2[1024*224];    // per (b,chunk16) raw-x weighted sums
__device__ ull   g_KD2[1024*7];     // per (b,chunk16) {K, D}

// ---------------------------------------------------------------------------
// attn_pass (R15 config; P phase unroll 8): grid 1024 = 64 b x 16 chunks.
// ---------------------------------------------------------------------------
__global__ void __launch_bounds__(128,4) attn_pass(const float* __restrict__ inp)
{
    extern __shared__ ull sm[];
    ull* Xs = sm;            // [128][34]
    ull* As = sm + 4352;     // [128][10]
    ull* Ub = sm + 5632;     // [7] (+1 pad)
    ull* Ug = sm + 5640;     // [7][32]

    int tid = threadIdx.x, blk = blockIdx.x;
    int b = blk >> 4, chunk = blk & 15;

    pdl_trigger();

    ull p2[7]; ull kd2 = 0ull;
    #pragma unroll
    for (int i = 0; i < 7; i++) p2[i] = 0ull;

    const ulonglong2* in4 = (const ulonglong2*)inp + (size_t)(b*4096 + chunk*256)*16;
    int w8 = tid >> 5, cp = tid & 31;

    for (int pass = 0; pass < 2; pass++) {
        __syncthreads();
        const ulonglong2* src = in4 + pass*128*16;
        #pragma unroll
        for (int k = 0; k < 16; k++) {
            int idx = tid + k*128;
            int t = idx >> 4, c = idx & 15;
            ulonglong2 v = src[idx];
            *reinterpret_cast<ulonglong2*>(Xs + t*34 + c*2) = v;
        }
        if (pass == 0) {
            pdl_wait();
            for (int i = tid; i < 224; i += 128) Ug[i] = g_ug2[b*224 + i];
            if (tid < 7) Ub[tid] = g_ub2[b*7 + tid];
        }
        __syncthreads();
        // ---- token phase ----
        {
            ull* xrow = Xs + tid*34;
            ull sa = 0ull, qa = 0ull, acc[7];
            #pragma unroll
            for (int i = 0; i < 7; i++) acc[i] = 0ull;
            #pragma unroll
            for (int q2 = 0; q2 < 16; q2++) {
                ulonglong2 xv = *reinterpret_cast<const ulonglong2*>(xrow + q2*2);
                sa = add2(add2(sa, xv.x), xv.y);
                qa = fma2(xv.y, xv.y, fma2(xv.x, xv.x, qa));
                #pragma unroll
                for (int i = 0; i < 7; i++) {
                    ulonglong2 u = *reinterpret_cast<const ulonglong2*>(Ug + i*32 + q2*2);
                    acc[i] = fma2(xv.y, u.y, fma2(xv.x, u.x, acc[i]));
                }
            }
            float s0,s1,q0,q1; unpack2(sa,s0,s1); unpack2(qa,q0,q1);
            float m    = (s0 + s1) * 0.015625f;
            float varr = fmaf(-m, m, (q0 + q1) * 0.015625f) + LN_EPS;
            float inv  = rsqrtf(varr);
            float stdv = varr * inv;
            float d[7];
            #pragma unroll
            for (int i = 0; i < 7; i++) {
                float a0,a1,ub,su;
                unpack2(acc[i], a0, a1);
                unpack2(Ub[i], ub, su);
                d[i] = fmaf(fmaf(-m, su, a0 + a1), inv, ub);
            }
            float mx = d[0];
            #pragma unroll
            for (int i = 1; i < 7; i++) mx = fmaxf(mx, d[i]);
            float e[7], se = 0.f;
            #pragma unroll
            for (int i = 0; i < 7; i++) { e[i] = __expf(d[i] - mx); se += e[i]; }
            float rinv = 1.0f / se;
            float wv[7];
            #pragma unroll
            for (int i = 0; i < 7; i++) wv[i] = fmaf(e[i], rinv, EPSA) * inv;
            ull* arow = As + tid*10;
            *reinterpret_cast<ulonglong2*>(arow + 0) =
                make_ulonglong2(pack2(wv[0],wv[0]), pack2(wv[1],wv[1]));
            *reinterpret_cast<ulonglong2*>(arow + 2) =
                make_ulonglong2(pack2(wv[2],wv[2]), pack2(wv[3],wv[3]));
            *reinterpret_cast<ulonglong2*>(arow + 4) =
                make_ulonglong2(pack2(wv[4],wv[4]), pack2(wv[5],wv[5]));
            *reinterpret_cast<ulonglong2*>(arow + 6) =
                make_ulonglong2(pack2(wv[6],wv[6]), pack2(wv[6],wv[6]));
            xrow[32] = pack2(m, stdv);
        }
        __syncthreads();
        // ---- P phase (unroll 8: immediate-offset LDS, longer sched window) ----
        {
            int tb = w8 * 32;
            #pragma unroll 8
            for (int j = 0; j < 32; j++) {
                int t = tb + j;
                ull xv = Xs[t*34 + cp];
                const ulonglong2* ap = reinterpret_cast<const ulonglong2*>(As + t*10);
                ulonglong2 a01 = ap[0], a23 = ap[1], a45 = ap[2];
                ull a6 = As[t*10 + 6];
                p2[0] = fma2(a01.x, xv, p2[0]);
                p2[1] = fma2(a01.y, xv, p2[1]);
                p2[2] = fma2(a23.x, xv, p2[2]);
                p2[3] = fma2(a23.y, xv, p2[3]);
                p2[4] = fma2(a45.x, xv, p2[4]);
                p2[5] = fma2(a45.y, xv, p2[5]);
                p2[6] = fma2(a6,    xv, p2[6]);
            }
        }
        // ---- KD phase ----
        if (tid < 112) {
            int i = tid >> 4, tg = tid & 15;
            #pragma unroll
            for (int j = 0; j < 8; j++) {
                int t = j*16 + tg;
                kd2 = fma2(As[t*10 + i], Xs[t*34 + 32], kd2);
            }
        }
    }
    __syncthreads();
    #pragma unroll
    for (int i = 0; i < 7; i++) Xs[w8*224 + i*32 + cp] = p2[i];
    ull* redKD = Xs + 896;
    if (tid < 112) redKD[tid] = kd2;
    __syncthreads();
    for (int o = tid; o < 224; o += 128) {
        ull s = 0ull;
        #pragma unroll
        for (int h = 0; h < 4; h++) s = add2(s, Xs[h*224 + o]);
        g_P2[blk*224 + o] = s;
    }
    if (tid >= 112 && tid < 119) {
        int i = tid - 112;
        ull s = 0ull;
        #pragma unroll
        for (int tg = 0; tg < 16; tg++) s = add2(s, redKD[i*16 + tg]);
        g_KD2[blk*7 + i] = s;
    }
}

// ---------------------------------------------------------------------------
// slot-side (R15 config): bulk-copied weights; weight-shared GRU/P6; PDL.
// ---------------------------------------------------------------------------
#define OWQ   0
#define OWK   4096
#define OWV   8192
#define OWIH  12288
#define OWHH  24576
#define OW1   36864
#define OW2   45056
#define OXA   53248
#define OUPD  53696
#define OH    54144
#define ONEW  54592
#define OY1   55040
#define SLOT_SMEM (55936*4)

__device__ __forceinline__ void warp_ln(const float* src, float* dst,
                                        const float* __restrict__ g,
                                        const float* __restrict__ be,
                                        int w, int lane) {
    float v0 = src[w*64 + lane], v1 = src[w*64 + 32 + lane];
    float s = v0 + v1, ss = v0*v0 + v1*v1;
    #pragma unroll
    for (int o = 16; o; o >>= 1) {
        s  += __shfl_xor_sync(0xffffffffu, s,  o);
        ss += __shfl_xor_sync(0xffffffffu, ss, o);
    }
    float m   = s * 0.015625f;
    float inv = rsqrtf(ss * 0.015625f - m*m + LN_EPS);
    dst[w*64 + lane]      = (v0 - m)*inv*g[lane]      + be[lane];
    dst[w*64 + 32 + lane] = (v1 - m)*inv*g[lane + 32] + be[lane + 32];
}

__device__ __forceinline__ float rotdot64(const float* Wrow, const float* v, int c) {
    float a0 = 0.f, a1 = 0.f;
    #pragma unroll 8
    for (int s = 0; s < 64; s += 2) {
        int d0 = (c + s) & 63, d1 = (c + s + 1) & 63;
        a0 = fmaf(Wrow[d0], v[d0], a0);
        a1 = fmaf(Wrow[d1], v[d1], a1);
    }
    return a0 + a1;
}

__device__ void do_prep(int b, int tid, float* fs,
                        const float* __restrict__ bq, const float* __restrict__ bk,
                        const float* __restrict__ gsl, const float* __restrict__ besl,
                        const float* __restrict__ gin, const float* __restrict__ bein)
{
    float* sS = fs + OXA;
    float* sQ = fs + OUPD;
    float* sU = fs + OY1;
    int w = tid >> 5, lane = tid & 31;
    if (w < 7) warp_ln(fs + OH, sS, gsl, besl, w, lane);
    __syncthreads();
    if (tid < 448) {
        int i = tid >> 6, c = tid & 63;
        sQ[tid] = bq[c] + rotdot64(fs + OWQ + c*64, sS + i*64, c);
    }
    __syncthreads();
    if (tid < 448) {
        int i = tid >> 6, e = tid & 63;
        float a0 = 0.f, a1 = 0.f;
        #pragma unroll 8
        for (int c = 0; c < 64; c += 2) {
            a0 = fmaf(sQ[i*64 + c],   fs[OWK + c*64 + e],     a0);
            a1 = fmaf(sQ[i*64 + c+1], fs[OWK + (c+1)*64 + e], a1);
        }
        float u = a0 + a1;
        sU[tid] = u;
        ((float*)g_ug2)[b*448 + tid] = u * gin[e] * SCALE;
    }
    __syncthreads();
    if (w < 7) {
        float u0 = sU[w*64 + lane], u1 = sU[w*64 + 32 + lane];
        float su = u0*gin[lane]  + u1*gin[lane + 32];
        float ub = u0*bein[lane] + u1*bein[lane + 32]
                 + sQ[w*64 + lane]*bk[lane] + sQ[w*64 + 32 + lane]*bk[lane + 32];
        #pragma unroll
        for (int o = 16; o; o >>= 1) {
            su += __shfl_xor_sync(0xffffffffu, su, o);
            ub += __shfl_xor_sync(0xffffffffu, ub, o);
        }
        if (lane == 0) g_ub2[b*7 + w] = pack2(SCALE*ub, SCALE*su);
    }
}

__global__ void __launch_bounds__(512,1)
slot_begin(const float* __restrict__ noise, const float* __restrict__ mu,
           const float* __restrict__ sigma,
           const float* __restrict__ Wq, const float* __restrict__ bq,
           const float* __restrict__ Wk, const float* __restrict__ bk,
           const float* __restrict__ gsl, const float* __restrict__ besl,
           const float* __restrict__ gin, const float* __restrict__ bein)
{
    extern __shared__ float fs[];
    __shared__ ull mbar_s;
    int b = blockIdx.x, tid = threadIdx.x;
    uint32_t sbase = smem_u32(fs);
    uint32_t mbar  = smem_u32(&mbar_s);
    pdl_trigger();
    if (tid == 0) mbar_init(mbar, 1);
    __syncthreads();
    if (tid == 0) {
        mbar_expect(mbar, 2*16384);
        bulk_cp(sbase + OWQ*4, Wq, 16384, mbar);
        bulk_cp(sbase + OWK*4, Wk, 16384, mbar);
    }
    if (tid < 448) {
        int c = tid & 63;
        float v = fmaf(sigma[c], noise[b*448 + tid], mu[c]);
        g_slots[b*448 + tid] = v;
        fs[OH + tid] = v;
    }
    __syncthreads();
    mbar_waitp(mbar, 0);
    do_prep(b, tid, fs, bq, bk, gsl, besl, gin, bein);
}

__global__ void __launch_bounds__(512,1)
slot_step(const float* __restrict__ Wv, const float* __restrict__ bv,
          const float* __restrict__ W_ih, const float* __restrict__ W_hh,
          const float* __restrict__ b_ih, const float* __restrict__ b_hh,
          const float* __restrict__ W1, const float* __restrict__ b1,
          const float* __restrict__ W2, const float* __restrict__ b2,
          const float* __restrict__ gin, const float* __restrict__ bein,
          const float* __restrict__ gff, const float* __restrict__ beff,
          const float* __restrict__ Wq, const float* __restrict__ bq,
          const float* __restrict__ Wk, const float* __restrict__ bk,
          const float* __restrict__ gsl, const float* __restrict__ besl,
          float* __restrict__ outp, int doprep)
{
    extern __shared__ float fs[];
    __shared__ ull mbar_s;
    __shared__ float sK[7], sD[7];
    float* sxa  = fs + OXA;
    float* supd = fs + OUPD;
    float* sh   = fs + OH;
    float* snew = fs + ONEW;
    float* sff  = fs + OXA;
    float* sy1  = fs + OY1;
    int b = blockIdx.x, tid = threadIdx.x;
    int w = tid >> 5, lane = tid & 31;
    const float* gP = (const float*)g_P2;
    uint32_t sbase = smem_u32(fs);
    uint32_t mbar  = smem_u32(&mbar_s);

    pdl_trigger();
    if (tid == 0) mbar_init(mbar, 1);
    __syncthreads();
    if (tid == 0) {
        uint32_t total = 16384 + 2*49152 + 32768 + (doprep ? 2*16384 : 0);
        mbar_expect(mbar, total);
        bulk_cp(sbase + OWV*4,  Wv,   16384, mbar);
        bulk_cp(sbase + OWIH*4, W_ih, 49152, mbar);
        bulk_cp(sbase + OWHH*4, W_hh, 49152, mbar);
        bulk_cp(sbase + OW1*4,  W1,   32768, mbar);
        if (doprep) {
            bulk_cp(sbase + OWQ*4, Wq, 16384, mbar);
            bulk_cp(sbase + OWK*4, Wk, 16384, mbar);
        }
    }

    pdl_wait();
    // P0
    if (tid < 448) {
        float s = 0.f;
        #pragma unroll
        for (int ch = 0; ch < 16; ch++) s += gP[(b*16 + ch)*448 + tid];
        sxa[tid] = s;
        sh[tid]  = g_slots[b*448 + tid];
    }
    if (tid < 7) {
        float K = 0.f, D = 0.f;
        #pragma unroll
        for (int ch = 0; ch < 16; ch++) {
            float k0, d0; unpack2(g_KD2[(b*16 + ch)*7 + tid], k0, d0);
            K += k0; D += d0;
        }
        sK[tid] = K; sD[tid] = D;
    }
    __syncthreads();
    // P1
    if (tid < 448) {
        int e = tid & 63, i = tid >> 6;
        sxa[tid] = fmaf((sxa[tid] - sK[i]) / sD[i], gin[e], bein[e]);
    }
    __syncthreads();
    mbar_waitp(mbar, 0);
    // P2
    if (tid < 448) {
        int c = tid & 63, i = tid >> 6;
        supd[tid] = bv[c] + rotdot64(fs + OWV + c*64, sxa + i*64, c);
    }
    __syncthreads();
    // P3a: GRU dot partials, weight-shared (scratch = OW2 region)
    if (tid < 128) {
        int c = tid & 63, h = tid >> 6;
        const float* wir = fs + OWIH + c*64;
        const float* wiz = fs + OWIH + (64 + c)*64;
        const float* win = fs + OWIH + (128 + c)*64;
        const float* whr = fs + OWHH + c*64;
        const float* whz = fs + OWHH + (64 + c)*64;
        const float* whn = fs + OWHH + (128 + c)*64;
        float air[7], aiz[7], ain[7], ahr[7], ahz[7], ahn[7];
        #pragma unroll
        for (int i = 0; i < 7; i++) { air[i]=0.f; aiz[i]=0.f; ain[i]=0.f; ahr[i]=0.f; ahz[i]=0.f; ahn[i]=0.f; }
        int dbase = h * 32;
        #pragma unroll 4
        for (int s = 0; s < 32; s++) {
            int d = dbase + ((c + s) & 31);
            float wr_ = wir[d], wz_ = wiz[d], wn_ = win[d];
            float vr_ = whr[d], vz_ = whz[d], vn_ = whn[d];
            #pragma unroll
            for (int i = 0; i < 7; i++) {
                float xv = supd[i*64 + d];
                float hv = sh[i*64 + d];
                air[i] = fmaf(xv, wr_, air[i]);
                aiz[i] = fmaf(xv, wz_, aiz[i]);
                ain[i] = fmaf(xv, wn_, ain[i]);
                ahr[i] = fmaf(hv, vr_, ahr[i]);
                ahz[i] = fmaf(hv, vz_, ahz[i]);
                ahn[i] = fmaf(hv, vn_, ahn[i]);
            }
        }
        float* scr = fs + OW2 + tid*42;
        #pragma unroll
        for (int i = 0; i < 7; i++) {
            scr[i*6+0] = air[i]; scr[i*6+1] = aiz[i]; scr[i*6+2] = ain[i];
            scr[i*6+3] = ahr[i]; scr[i*6+4] = ahz[i]; scr[i*6+5] = ahn[i];
        }
    }
    __syncthreads();
    // P3b
    if (tid < 448) {
        int c = tid & 63, i = tid >> 6;
        const float* s0 = fs + OW2 + c*42 + i*6;
        const float* s1 = fs + OW2 + (64 + c)*42 + i*6;
        float gir = s0[0] + s1[0] + b_ih[c];
        float giz = s0[1] + s1[1] + b_ih[64 + c];
        float gin_ = s0[2] + s1[2] + b_ih[128 + c];
        float ghr = s0[3] + s1[3] + b_hh[c];
        float ghz = s0[4] + s1[4] + b_hh[64 + c];
        float ghn = s0[5] + s1[5] + b_hh[128 + c];
        float rg = 1.0f / (1.0f + __expf(-(gir + ghr)));
        float zg = 1.0f / (1.0f + __expf(-(giz + ghz)));
        float ng = tanhf(fmaf(rg, ghn, gin_));
        snew[tid] = fmaf(zg, sh[tid] - ng, ng);
    }
    __syncthreads();
    // Phase B: W2 copy
    if (tid == 0) {
        mbar_expect(mbar, 32768);
        bulk_cp(sbase + OW2*4, W2, 32768, mbar);
    }
    // P4
    if (w < 7) warp_ln(snew, sff, gff, beff, w, lane);
    __syncthreads();
    // P5
    for (int idx = tid; idx < 896; idx += 512) {
        int i = idx >> 7, r = idx & 127;
        const float* wr = fs + OW1 + r*64;
        const float* v  = sff + i*64;
        float a0 = 0.f, a1 = 0.f;
        #pragma unroll 8
        for (int s = 0; s < 64; s += 2) {
            int d0 = (r + s) & 63, d1 = (r + s + 1) & 63;
            a0 = fmaf(wr[d0], v[d0], a0);
            a1 = fmaf(wr[d1], v[d1], a1);
        }
        sy1[idx] = fmaxf(b1[r] + a0 + a1, 0.0f);
    }
    __syncthreads();
    mbar_waitp(mbar, 1);
    // P6a
    if (tid < 128) {
        int c = tid & 63, rh = tid >> 6;
        const float* wr = fs + OW2 + c*128;
        float a[7];
        #pragma unroll
        for (int i = 0; i < 7; i++) a[i] = 0.f;
        int rbase = rh * 64;
        #pragma unroll 4
        for (int s = 0; s < 64; s++) {
            int r = rbase + ((c + s) & 63);
            float wv = wr[r];
            #pragma unroll
            for (int i = 0; i < 7; i++)
                a[i] = fmaf(sy1[i*128 + r], wv, a[i]);
        }
        float* ps = fs + OXA + tid*7;
        #pragma unroll
        for (int i = 0; i < 7; i++) ps[i] = a[i];
    }
    __syncthreads();
    // P6b
    if (tid < 448) {
        int c = tid & 63, i = tid >> 6;
        float a = fs[OXA + c*7 + i] + fs[OXA + (64 + c)*7 + i];
        float vout = snew[tid] + b2[c] + a;
        g_slots[b*448 + tid] = vout;
        sh[tid] = vout;
        if (outp) outp[b*448 + tid] = vout;
    }
    if (doprep) {
        __syncthreads();
        do_prep(b, tid, fs, bq, bk, gsl, besl, gin, bein);
    }
}

// ---------------------------------------------------------------------------
extern "C" void kernel_launch(void* const* d_in, const int* in_sizes, int n_in,
                              void* d_out, int out_size)
{
    const float* inputs = (const float*)d_in[0];
    const float* noise  = (const float*)d_in[2];
    const float* mu     = (const float*)d_in[3];
    const float* sigma  = (const float*)d_in[4];
    const float* Wq     = (const float*)d_in[5];
    const float* bq     = (const float*)d_in[6];
    const float* Wk     = (const float*)d_in[7];
    const float* bk     = (const float*)d_in[8];
    const float* Wv     = (const float*)d_in[9];
    const float* bv     = (const float*)d_in[10];
    const float* W_ih   = (const float*)d_in[11];
    const float* W_hh   = (const float*)d_in[12];
    const float* b_ih   = (const float*)d_in[13];
    const float* b_hh   = (const float*)d_in[14];
    const float* W1     = (const float*)d_in[15];
    const float* b1     = (const float*)d_in[16];
    const float* W2     = (const float*)d_in[17];
    const float* b2     = (const float*)d_in[18];
    const float* gin    = (const float*)d_in[19];
    const float* bein   = (const float*)d_in[20];
    const float* gsl    = (const float*)d_in[21];
    const float* besl   = (const float*)d_in[22];
    const float* gff    = (const float*)d_in[23];
    const float* beff   = (const float*)d_in[24];

    const int ATTN_SMEM = 5864 * 8;
    static int configured = 0;
    if (!configured) {
        cudaFuncSetAttribute(attn_pass, cudaFuncAttributeMaxDynamicSharedMemorySize, ATTN_SMEM);
        cudaFuncSetAttribute(slot_begin, cudaFuncAttributeMaxDynamicSharedMemorySize, SLOT_SMEM);
        cudaFuncSetAttribute(slot_step, cudaFuncAttributeMaxDynamicSharedMemorySize, SLOT_SMEM);
        configured = 1;
    }

    cudaLaunchAttribute pdlAttr[1];
    pdlAttr[0].id = cudaLaunchAttributeProgrammaticStreamSerialization;
    pdlAttr[0].val.programmaticStreamSerializationAllowed = 1;

    {
        cudaLaunchConfig_t cfg = {};
        cfg.gridDim = dim3(64,1,1); cfg.blockDim = dim3(512,1,1);
        cfg.dynamicSmemBytes = SLOT_SMEM;
        cudaLaunchKernelEx(&cfg, slot_begin, noise, mu, sigma, Wq, bq, Wk, bk,
                           gsl, besl, gin, bein);
    }
    for (int it = 0; it < 3; it++) {
        {
            cudaLaunchConfig_t cfg = {};
            cfg.gridDim = dim3(1024,1,1); cfg.blockDim = dim3(128,1,1);
            cfg.dynamicSmemBytes = ATTN_SMEM;
            cfg.attrs = pdlAttr; cfg.numAttrs = 1;
            cudaLaunchKernelEx(&cfg, attn_pass, inputs);
        }
        {
            cudaLaunchConfig_t cfg = {};
            cfg.gridDim = dim3(64,1,1); cfg.blockDim = dim3(512,1,1);
            cfg.dynamicSmemBytes = SLOT_SMEM;
            cfg.attrs = pdlAttr; cfg.numAttrs = 1;
            cudaLaunchKernelEx(&cfg, slot_step, Wv, bv, W_ih, W_hh, b_ih, b_hh,
                               W1, b1, W2, b2, gin, bein, gff, beff,
                               Wq, bq, Wk, bk, gsl, besl,
                               it == 2 ? (float*)d_out : (float*)nullptr,
                               it == 2 ? 0 : 1);
        }
    }
}